// round 11
// baseline (speedup 1.0000x reference)
#include <cuda_runtime.h>
#include <cuda_bf16.h>
#include <cstdint>

#define NROWS 8192
#define DDIM  256
#define PP    3
#define KC    32
#define NCHUNK (NROWS / KC)      // 256

// gemm1: persistent ticket kernel, M=32 tiles
#define TILE_M   32
#define G1_TILES 768             // 256 bx * 3 p
#define G1_CTAS  296             // 2 * 148
// smem layout per stage, 80B-padded rows
#define APITCH 80
#define AH_OFF 0
#define AL_OFF 2560
#define BH_OFF 5120
#define BL_OFF 25600
#define STG    46080
#define G1_SMEM (2 * STG)        // 92160

// ---- scratch (device globals; no allocation allowed) ----
__device__ __align__(16) float g_M[PP * NROWS * DDIM];
__device__ __align__(16) float g_T[NROWS * 3 * DDIM];
__device__ __align__(16) float g_Wc[3 * DDIM * DDIM];
__device__ __align__(16) float g_bias[DDIM];
__device__ __align__(16) __nv_bfloat16 g_Xth[DDIM * NROWS];   // X^T hi  [d][k]
__device__ __align__(16) __nv_bfloat16 g_Xtl[DDIM * NROWS];   // X^T lo  [d][k]
__device__ int g_ticket;

// =============== helpers ===============
__device__ __forceinline__ unsigned smem_u32(const void* p) {
    return (unsigned)__cvta_generic_to_shared(p);
}
__device__ __forceinline__ void cp16(unsigned dst, const void* src) {
    asm volatile("cp.async.cg.shared.global [%0], [%1], 16;" :: "r"(dst), "l"(src));
}
__device__ __forceinline__ void cp_commit() { asm volatile("cp.async.commit_group;"); }
__device__ __forceinline__ void cp_wait0()  { asm volatile("cp.async.wait_group 0;"); }

__device__ __forceinline__ void sts64(uint32_t addr, uint32_t v0, uint32_t v1) {
    asm volatile("st.shared.v2.b32 [%0], {%1, %2};" :: "r"(addr), "r"(v0), "r"(v1) : "memory");
}

// ldmatrix x4 (sm_75+, legal at plain sm_103)
__device__ __forceinline__ void ldsm4(uint32_t* r, uint32_t addr) {
    asm volatile("ldmatrix.sync.aligned.m8n8.x4.shared.b16 {%0,%1,%2,%3}, [%4];"
                 : "=r"(r[0]), "=r"(r[1]), "=r"(r[2]), "=r"(r[3]) : "r"(addr));
}

// HMMA m16n8k16 bf16
__device__ __forceinline__ void mma16816(float* c, const uint32_t* a,
                                         uint32_t b0, uint32_t b1) {
    asm("mma.sync.aligned.m16n8k16.row.col.f32.bf16.bf16.f32 "
        "{%0,%1,%2,%3}, {%4,%5,%6,%7}, {%8,%9}, {%0,%1,%2,%3};"
        : "+f"(c[0]), "+f"(c[1]), "+f"(c[2]), "+f"(c[3])
        : "r"(a[0]), "r"(a[1]), "r"(a[2]), "r"(a[3]), "r"(b0), "r"(b1));
}

// packed f32x2 FMA for epilogue gemm
__device__ __forceinline__ unsigned long long pack2(float v) {
    unsigned long long r; unsigned u = __float_as_uint(v);
    asm("mov.b64 %0, {%1, %1};" : "=l"(r) : "r"(u));
    return r;
}
__device__ __forceinline__ void ffma2(unsigned long long& c, unsigned long long a,
                                      unsigned long long b) {
    asm("fma.rn.f32x2 %0, %1, %2, %0;" : "+l"(c) : "l"(a), "l"(b));
}
__device__ __forceinline__ float2 unpack2(unsigned long long v) {
    unsigned lo, hi;
    asm("mov.b64 {%0, %1}, %2;" : "=r"(lo), "=r"(hi) : "l"(v));
    float2 f; f.x = __uint_as_float(lo); f.y = __uint_as_float(hi); return f;
}

// =============== X^T transpose + bf16 hi/lo split ===============
__global__ void xt_kernel(const float* __restrict__ X) {
    __shared__ float tile[32][33];
    int k0 = blockIdx.x * 32, d0 = blockIdx.y * 32;
    int tx = threadIdx.x, ty = threadIdx.y;     // 32 x 8
    #pragma unroll
    for (int i = 0; i < 4; i++)
        tile[ty + 8 * i][tx] = X[(size_t)(k0 + ty + 8 * i) * DDIM + d0 + tx];
    __syncthreads();
    #pragma unroll
    for (int i = 0; i < 4; i++) {
        int d = d0 + ty + 8 * i, k = k0 + tx;
        float v = tile[tx][ty + 8 * i];
        __nv_bfloat16 h = __float2bfloat16(v);
        __nv_bfloat16 l = __float2bfloat16(v - __bfloat162float(h));
        g_Xth[(size_t)d * NROWS + k] = h;
        g_Xtl[(size_t)d * NROWS + k] = l;
    }
}

// =============== prep: Wc transpose + fused bias + ticket reset ===============
__global__ void prep_kernel(const float* __restrict__ W, const float* __restrict__ b) {
    int idx = blockIdx.x * blockDim.x + threadIdx.x;
    if (idx == 0) g_ticket = 0;
    if (idx < 3 * DDIM * DDIM) {
        int kk = idx & (DDIM - 1);
        int rd = idx >> 8;
        int d  = rd & (DDIM - 1);
        int r  = rd >> 8;
        g_Wc[(r * DDIM + kk) * DDIM + d] = W[idx];
    }
    if (idx < DDIM)
        g_bias[idx] = b[idx] + 3.0f * b[DDIM + idx] + 6.0f * b[2 * DDIM + idx];
}

// =============== gemm1: M_p = A_p @ X  (HMMA bf16 3-term split) ===============
// Persistent: 296 CTAs pull 32x256 tiles via global ticket. 256 threads,
// 8 warps side-by-side in N (warp tile 32x32: 2 m16-frags x 4 n8-frags).
__global__ __launch_bounds__(256, 2)
void gemm1_kernel(const float* __restrict__ A) {
    extern __shared__ char sm[];
    __shared__ int s_tile;

    const int tid  = threadIdx.x;
    const int wid  = tid >> 5;
    const int lane = tid & 31;
    const int g    = lane >> 2;
    const int t4   = lane & 3;
    const int n0w  = wid * 32;

    // --- producer addresses (tile-independent parts) ---
    const int arw = tid >> 3, acl = tid & 7;        // A: 32 rows x 8 float4
    const uint32_t aHiDst = smem_u32(sm) + AH_OFF + arw * APITCH + acl * 8;
    const uint32_t aLoDst = smem_u32(sm) + AL_OFF + arw * APITCH + acl * 8;
    const __nv_bfloat16* bSrc[8];
    uint32_t bDst[8];
    #pragma unroll
    for (int j = 0; j < 8; j++) {
        int idx = j * 256 + tid;            // 0..2047
        int half = idx >> 10;               // 0 hi, 1 lo
        int q = idx & 1023;
        int n = q >> 2, c = q & 3;
        bSrc[j] = (half ? g_Xtl : g_Xth) + (size_t)n * NROWS + c * 8;
        bDst[j] = smem_u32(sm) + (half ? BL_OFF : BH_OFF) + n * APITCH + c * 16;
    }

    // --- ldmatrix base addresses ---
    const int aRow = (lane & 7) + ((lane >> 3) & 1) * 8;
    const int aCol = ((lane >> 4) & 1) * 16;
    const uint32_t aBaseH = smem_u32(sm) + AH_OFF + aRow * APITCH + aCol;
    const uint32_t aBaseL = smem_u32(sm) + AL_OFF + aRow * APITCH + aCol;
    const int bRow = n0w + ((lane >> 4) & 1) * 8 + (lane & 7);
    const int bCol = ((lane >> 3) & 1) * 16;
    const uint32_t bBaseH = smem_u32(sm) + BH_OFF + bRow * APITCH + bCol;
    const uint32_t bBaseL = smem_u32(sm) + BL_OFF + bRow * APITCH + bCol;

    for (;;) {
        if (tid == 0) s_tile = atomicAdd(&g_ticket, 1);
        __syncthreads();
        const int tile = s_tile;
        if (tile >= G1_TILES) break;
        const int p = tile >> 8, bx = tile & 255;
        const float* aSrc = A + (size_t)p * NROWS * NROWS
                              + (size_t)(bx * TILE_M + arw) * NROWS + acl * 4;

        float acc[2][4][4];
        #pragma unroll
        for (int mf = 0; mf < 2; mf++)
            #pragma unroll
            for (int nf = 0; nf < 4; nf++)
                #pragma unroll
                for (int q = 0; q < 4; q++) acc[mf][nf][q] = 0.0f;

        // prologue: fill stage 0
        {
            float4 v = *reinterpret_cast<const float4*>(aSrc);
            #pragma unroll
            for (int j = 0; j < 8; j++) cp16(bDst[j], bSrc[j]);
            cp_commit();
            __nv_bfloat162 h01 = __floats2bfloat162_rn(v.x, v.y);
            __nv_bfloat162 h23 = __floats2bfloat162_rn(v.z, v.w);
            float2 f01 = __bfloat1622float2(h01);
            float2 f23 = __bfloat1622float2(h23);
            __nv_bfloat162 l01 = __floats2bfloat162_rn(v.x - f01.x, v.y - f01.y);
            __nv_bfloat162 l23 = __floats2bfloat162_rn(v.z - f23.x, v.w - f23.y);
            sts64(aHiDst, *reinterpret_cast<uint32_t*>(&h01), *reinterpret_cast<uint32_t*>(&h23));
            sts64(aLoDst, *reinterpret_cast<uint32_t*>(&l01), *reinterpret_cast<uint32_t*>(&l23));
            cp_wait0();
            __syncthreads();
        }

        for (int t = 0; t < NCHUNK; t++) {
            const int cur = t & 1, nxt = cur ^ 1;
            const bool more = (t + 1 < NCHUNK);
            float4 av;
            if (more) {
                av = *reinterpret_cast<const float4*>(aSrc + (size_t)(t + 1) * KC);
                #pragma unroll
                for (int j = 0; j < 8; j++)
                    cp16(bDst[j] + nxt * STG, bSrc[j] + (size_t)(t + 1) * KC);
                cp_commit();
            }

            const uint32_t soff = cur * STG;
            #pragma unroll
            for (int j16 = 0; j16 < 2; j16++) {
                const int kb = j16 * 32;
                uint32_t ah[2][4], al[2][4];
                ldsm4(ah[0], aBaseH + soff + kb);
                ldsm4(ah[1], aBaseH + soff + 16 * APITCH + kb);
                ldsm4(al[0], aBaseL + soff + kb);
                ldsm4(al[1], aBaseL + soff + 16 * APITCH + kb);
                #pragma unroll
                for (int np = 0; np < 2; np++) {
                    uint32_t bh[4], bl[4];
                    ldsm4(bh, bBaseH + soff + np * 16 * APITCH + kb);
                    ldsm4(bl, bBaseL + soff + np * 16 * APITCH + kb);
                    #pragma unroll
                    for (int h = 0; h < 2; h++) {
                        const int nf = 2 * np + h;
                        uint32_t b0h = bh[2 * h], b1h = bh[2 * h + 1];
                        uint32_t b0l = bl[2 * h], b1l = bl[2 * h + 1];
                        #pragma unroll
                        for (int mf = 0; mf < 2; mf++) {
                            mma16816(acc[mf][nf], ah[mf], b0h, b1h);
                            mma16816(acc[mf][nf], al[mf], b0h, b1h);
                            mma16816(acc[mf][nf], ah[mf], b0l, b1l);
                        }
                    }
                }
            }

            if (more) {
                __nv_bfloat162 h01 = __floats2bfloat162_rn(av.x, av.y);
                __nv_bfloat162 h23 = __floats2bfloat162_rn(av.z, av.w);
                float2 f01 = __bfloat1622float2(h01);
                float2 f23 = __bfloat1622float2(h23);
                __nv_bfloat162 l01 = __floats2bfloat162_rn(av.x - f01.x, av.y - f01.y);
                __nv_bfloat162 l23 = __floats2bfloat162_rn(av.z - f23.x, av.w - f23.y);
                sts64(aHiDst + nxt * STG, *reinterpret_cast<uint32_t*>(&h01),
                                          *reinterpret_cast<uint32_t*>(&h23));
                sts64(aLoDst + nxt * STG, *reinterpret_cast<uint32_t*>(&l01),
                                          *reinterpret_cast<uint32_t*>(&l23));
            }
            cp_wait0();
            __syncthreads();
        }

        // epilogue: C frags -> g_M
        float* Mout = g_M + (size_t)p * NROWS * DDIM + (size_t)(bx * TILE_M) * DDIM;
        #pragma unroll
        for (int mf = 0; mf < 2; mf++) {
            #pragma unroll
            for (int nf = 0; nf < 4; nf++) {
                int r = mf * 16 + g;
                int c = n0w + nf * 8 + 2 * t4;
                *reinterpret_cast<float2*>(Mout + (size_t)r * DDIM + c) =
                    make_float2(acc[mf][nf][0], acc[mf][nf][1]);
                *reinterpret_cast<float2*>(Mout + (size_t)(r + 8) * DDIM + c) =
                    make_float2(acc[mf][nf][2], acc[mf][nf][3]);
            }
        }
    }
}

// =============== combine: T = [X | S1 | S2] ===============
__global__ void combine_kernel(const float* __restrict__ X) {
    int idx = blockIdx.x * blockDim.x + threadIdx.x;
    if (idx >= NROWS * DDIM / 4) return;
    int n = idx >> 6;
    int c = (idx & 63) << 2;
    size_t off = (size_t)n * DDIM + c;
    float4 x  = *reinterpret_cast<const float4*>(X + off);
    float4 m0 = *reinterpret_cast<const float4*>(g_M + off);
    float4 m1 = *reinterpret_cast<const float4*>(g_M + (size_t)NROWS * DDIM + off);
    float4 m2 = *reinterpret_cast<const float4*>(g_M + 2 * (size_t)NROWS * DDIM + off);
    float4 s1, s2;
    s1.x = m0.x + m1.x + m2.x;  s1.y = m0.y + m1.y + m2.y;
    s1.z = m0.z + m1.z + m2.z;  s1.w = m0.w + m1.w + m2.w;
    s2.x = 0.5f * (s1.x * s1.x + m0.x * m0.x + m1.x * m1.x + m2.x * m2.x);
    s2.y = 0.5f * (s1.y * s1.y + m0.y * m0.y + m1.y * m1.y + m2.y * m2.y);
    s2.z = 0.5f * (s1.z * s1.z + m0.z * m0.z + m1.z * m1.z + m2.z * m2.z);
    s2.w = 0.5f * (s1.w * s1.w + m0.w * m0.w + m1.w * m1.w + m2.w * m2.w);
    float* T = g_T + (size_t)n * (3 * DDIM);
    *reinterpret_cast<float4*>(T + c)            = x;
    *reinterpret_cast<float4*>(T + DDIM + c)     = s1;
    *reinterpret_cast<float4*>(T + 2 * DDIM + c) = s2;
}

// =============== epilogue GEMM: out = relu(T @ Wc + bias) (FFMA2, N-split) =====
#define BM 64
#define BN 256
#define BNT 128
#define BK 16
#define THREADS 256
__global__ void __launch_bounds__(THREADS, 2)
gemm_epi_kernel(const float* __restrict__ Aop, const float* __restrict__ Bop,
                float* __restrict__ C, int K)
{
    __shared__ __align__(16) float As[2][BK][BM + 4];
    __shared__ __align__(16) float Bs[2][BK][BNT];

    const int tid = threadIdx.x;
    const int nOff = blockIdx.x * BNT;
    const float* Ap = Aop + (long long)blockIdx.y * BM * K;
    float*       Cp = C   + (long long)blockIdx.y * BM * DDIM + nOff;

    const int ar  = tid >> 2;
    const int akq = tid & 3;
    const float* aSrc = Ap + (long long)ar * K + akq * 4;
    const int tx = tid & 31;
    const int ty = tid >> 5;
    const int T = K / BK;

    unsigned long long acc[8][2];
    #pragma unroll
    for (int i = 0; i < 8; i++) { acc[i][0] = 0ull; acc[i][1] = 0ull; }

    {
        #pragma unroll
        for (int q = 0; q < 2; q++) {
            int id = tid + THREADS * q;
            int row = id >> 5, c4 = id & 31;
            cp16(smem_u32(&Bs[0][row][c4 * 4]), Bop + (long long)row * BN + nOff + c4 * 4);
        }
        cp_commit();
        float4 a = *reinterpret_cast<const float4*>(aSrc);
        As[0][4 * akq + 0][ar] = a.x; As[0][4 * akq + 1][ar] = a.y;
        As[0][4 * akq + 2][ar] = a.z; As[0][4 * akq + 3][ar] = a.w;
        cp_wait0();
        __syncthreads();
    }

    for (int t = 0; t < T; t++) {
        const int cur = t & 1, nxt = cur ^ 1;
        const bool more = (t + 1 < T);
        float4 aN;
        if (more) {
            aN = *reinterpret_cast<const float4*>(aSrc + (long long)(t + 1) * BK);
            #pragma unroll
            for (int q = 0; q < 2; q++) {
                int id = tid + THREADS * q;
                int row = id >> 5, c4 = id & 31;
                cp16(smem_u32(&Bs[nxt][row][c4 * 4]),
                     Bop + (long long)((t + 1) * BK + row) * BN + nOff + c4 * 4);
            }
            cp_commit();
        }
        #pragma unroll
        for (int k = 0; k < BK; k++) {
            float4 a0 = *reinterpret_cast<const float4*>(&As[cur][k][ty * 8]);
            float4 a1 = *reinterpret_cast<const float4*>(&As[cur][k][ty * 8 + 4]);
            ulonglong2 bq0 = *reinterpret_cast<const ulonglong2*>(&Bs[cur][k][tx * 4]);
            unsigned long long bb[2] = {bq0.x, bq0.y};
            float av[8] = {a0.x, a0.y, a0.z, a0.w, a1.x, a1.y, a1.z, a1.w};
            #pragma unroll
            for (int i = 0; i < 8; i++) {
                unsigned long long a2 = pack2(av[i]);
                ffma2(acc[i][0], a2, bb[0]);
                ffma2(acc[i][1], a2, bb[1]);
            }
        }
        if (more) {
            cp_wait0();
            As[nxt][4 * akq + 0][ar] = aN.x; As[nxt][4 * akq + 1][ar] = aN.y;
            As[nxt][4 * akq + 2][ar] = aN.z; As[nxt][4 * akq + 3][ar] = aN.w;
        }
        __syncthreads();
    }

    float4 bias0 = *reinterpret_cast<const float4*>(&g_bias[nOff + tx * 4]);
    #pragma unroll
    for (int i = 0; i < 8; i++) {
        float2 p0 = unpack2(acc[i][0]);
        float2 p1 = unpack2(acc[i][1]);
        float4 v0 = make_float4(p0.x, p0.y, p1.x, p1.y);
        v0.x = fmaxf(v0.x + bias0.x, 0.0f); v0.y = fmaxf(v0.y + bias0.y, 0.0f);
        v0.z = fmaxf(v0.z + bias0.z, 0.0f); v0.w = fmaxf(v0.w + bias0.w, 0.0f);
        *reinterpret_cast<float4*>(Cp + (long long)(ty * 8 + i) * DDIM + tx * 4) = v0;
    }
}

// =============== launch ===============
extern "C" void kernel_launch(void* const* d_in, const int* in_sizes, int n_in,
                              void* d_out, int out_size) {
    const float *X = nullptr, *A = nullptr, *W = nullptr, *b = nullptr;
    for (int i = 0; i < n_in; i++) {
        long long s = in_sizes[i];
        if      (s == (long long)PP * NROWS * NROWS) A = (const float*)d_in[i];
        else if (s == (long long)NROWS * DDIM)       X = (const float*)d_in[i];
        else if (s == (long long)PP * DDIM * DDIM)   W = (const float*)d_in[i];
        else if (s == (long long)PP * DDIM)          b = (const float*)d_in[i];
    }
    float *pT = nullptr, *pWc = nullptr;
    cudaGetSymbolAddress((void**)&pT,  g_T);
    cudaGetSymbolAddress((void**)&pWc, g_Wc);

    cudaFuncSetAttribute(gemm1_kernel,
                         cudaFuncAttributeMaxDynamicSharedMemorySize, G1_SMEM);

    prep_kernel<<<(3 * DDIM * DDIM + 255) / 256, 256>>>(W, b);
    xt_kernel<<<dim3(NROWS / 32, DDIM / 32), dim3(32, 8)>>>(X);
    gemm1_kernel<<<G1_CTAS, 256, G1_SMEM>>>(A);
    combine_kernel<<<(NROWS * DDIM / 4 + 255) / 256, 256>>>(X);
    gemm_epi_kernel<<<dim3(2, NROWS / BM), THREADS>>>(pT, pWc, (float*)d_out, 3 * DDIM);
}

// round 12
// speedup vs baseline: 1.1943x; 1.1943x over previous
#include <cuda_runtime.h>
#include <cuda_bf16.h>
#include <cstdint>

#define NROWS 8192
#define DDIM  256
#define PP    3
#define KC    32
#define NCHUNK (NROWS / KC)      // 256

// gemm1 smem layout (per stage), 80B-padded rows  (R9-identical)
#define APITCH 80
#define BPITCH 80
#define AH_OFF 0
#define AL_OFF 5120
#define BH_OFF 10240
#define BL_OFF 30720
#define STG    51200
#define G1_SMEM (2 * STG)        // 102400

// ---- scratch (device globals; no allocation allowed) ----
__device__ __align__(16) float g_M[PP * NROWS * DDIM];
__device__ __align__(16) float g_Wc[3 * DDIM * DDIM];
__device__ __align__(16) float g_bias[DDIM];
__device__ __align__(16) __nv_bfloat16 g_Xth[DDIM * NROWS];   // X^T hi  [d][k]
__device__ __align__(16) __nv_bfloat16 g_Xtl[DDIM * NROWS];   // X^T lo  [d][k]

// =============== helpers ===============
__device__ __forceinline__ unsigned smem_u32(const void* p) {
    return (unsigned)__cvta_generic_to_shared(p);
}
__device__ __forceinline__ void cp16(unsigned dst, const void* src) {
    asm volatile("cp.async.cg.shared.global [%0], [%1], 16;" :: "r"(dst), "l"(src));
}
__device__ __forceinline__ void cp_commit() { asm volatile("cp.async.commit_group;"); }
__device__ __forceinline__ void cp_wait0()  { asm volatile("cp.async.wait_group 0;"); }

__device__ __forceinline__ void sts64(uint32_t addr, uint32_t v0, uint32_t v1) {
    asm volatile("st.shared.v2.b32 [%0], {%1, %2};" :: "r"(addr), "r"(v0), "r"(v1) : "memory");
}

// ldmatrix x4 (sm_75+, legal at plain sm_103)
__device__ __forceinline__ void ldsm4(uint32_t* r, uint32_t addr) {
    asm volatile("ldmatrix.sync.aligned.m8n8.x4.shared.b16 {%0,%1,%2,%3}, [%4];"
                 : "=r"(r[0]), "=r"(r[1]), "=r"(r[2]), "=r"(r[3]) : "r"(addr));
}

// HMMA m16n8k16 bf16
__device__ __forceinline__ void mma16816(float* c, const uint32_t* a,
                                         uint32_t b0, uint32_t b1) {
    asm("mma.sync.aligned.m16n8k16.row.col.f32.bf16.bf16.f32 "
        "{%0,%1,%2,%3}, {%4,%5,%6,%7}, {%8,%9}, {%0,%1,%2,%3};"
        : "+f"(c[0]), "+f"(c[1]), "+f"(c[2]), "+f"(c[3])
        : "r"(a[0]), "r"(a[1]), "r"(a[2]), "r"(a[3]), "r"(b0), "r"(b1));
}

// packed f32x2 FMA for epilogue gemm
__device__ __forceinline__ unsigned long long pack2(float v) {
    unsigned long long r; unsigned u = __float_as_uint(v);
    asm("mov.b64 %0, {%1, %1};" : "=l"(r) : "r"(u));
    return r;
}
__device__ __forceinline__ void ffma2(unsigned long long& c, unsigned long long a,
                                      unsigned long long b) {
    asm("fma.rn.f32x2 %0, %1, %2, %0;" : "+l"(c) : "l"(a), "l"(b));
}
__device__ __forceinline__ float2 unpack2(unsigned long long v) {
    unsigned lo, hi;
    asm("mov.b64 {%0, %1}, %2;" : "=r"(lo), "=r"(hi) : "l"(v));
    float2 f; f.x = __uint_as_float(lo); f.y = __uint_as_float(hi); return f;
}

// =============== X^T transpose + bf16 hi/lo split ===============
__global__ void xt_kernel(const float* __restrict__ X) {
    __shared__ float tile[32][33];
    int k0 = blockIdx.x * 32, d0 = blockIdx.y * 32;
    int tx = threadIdx.x, ty = threadIdx.y;     // 32 x 8
    #pragma unroll
    for (int i = 0; i < 4; i++)
        tile[ty + 8 * i][tx] = X[(size_t)(k0 + ty + 8 * i) * DDIM + d0 + tx];
    __syncthreads();
    #pragma unroll
    for (int i = 0; i < 4; i++) {
        int d = d0 + ty + 8 * i, k = k0 + tx;
        float v = tile[tx][ty + 8 * i];
        __nv_bfloat16 h = __float2bfloat16(v);
        __nv_bfloat16 l = __float2bfloat16(v - __bfloat162float(h));
        g_Xth[(size_t)d * NROWS + k] = h;
        g_Xtl[(size_t)d * NROWS + k] = l;
    }
}

// =============== prep: Wc transpose + fused bias ===============
__global__ void prep_kernel(const float* __restrict__ W, const float* __restrict__ b) {
    int idx = blockIdx.x * blockDim.x + threadIdx.x;
    if (idx < 3 * DDIM * DDIM) {
        int kk = idx & (DDIM - 1);
        int rd = idx >> 8;
        int d  = rd & (DDIM - 1);
        int r  = rd >> 8;
        g_Wc[(r * DDIM + kk) * DDIM + d] = W[idx];
    }
    if (idx < DDIM)
        g_bias[idx] = b[idx] + 3.0f * b[DDIM + idx] + 6.0f * b[2 * DDIM + idx];
}

// =============== gemm1: M_p = A_p @ X  (HMMA bf16 3-term split) — R9 exact =====
// CTA: 64 x 256, BK=32, 256 threads, 8 warps (2 m-groups x 4 n-groups),
// warp tile 32 x 64 (2 m16-frags x 8 n8-frags). ldmatrix fragment loads.
__global__ __launch_bounds__(256, 2)
void gemm1_kernel(const float* __restrict__ A) {
    extern __shared__ char sm[];

    const int tid  = threadIdx.x;
    const int wid  = tid >> 5;
    const int lane = tid & 31;
    const int g    = lane >> 2;
    const int t4   = lane & 3;
    const int m0w  = (wid >> 2) * 32;
    const int n0w  = (wid & 3) * 64;
    const int bx = blockIdx.x, p = blockIdx.y;

    const float* Ap = A + (size_t)p * NROWS * NROWS + (size_t)bx * 64 * NROWS;

    const float* aSrc[2];
    uint32_t aHiDst[2], aLoDst[2];
    #pragma unroll
    for (int j = 0; j < 2; j++) {
        int idx = j * 256 + tid;
        int r = idx >> 3, c = idx & 7;
        aSrc[j]  = Ap + (size_t)r * NROWS + c * 4;
        aHiDst[j] = smem_u32(sm) + AH_OFF + r * APITCH + c * 8;
        aLoDst[j] = smem_u32(sm) + AL_OFF + r * APITCH + c * 8;
    }
    const __nv_bfloat16* bSrc[8];
    uint32_t bDst[8];
    #pragma unroll
    for (int j = 0; j < 8; j++) {
        int idx = j * 256 + tid;
        int half = idx >> 10;
        int q = idx & 1023;
        int n = q >> 2, c = q & 3;
        bSrc[j] = (half ? g_Xtl : g_Xth) + (size_t)n * NROWS + c * 8;
        bDst[j] = smem_u32(sm) + (half ? BL_OFF : BH_OFF) + n * BPITCH + c * 16;
    }

    const int aRow = m0w + (lane & 7) + ((lane >> 3) & 1) * 8;
    const int aCol = ((lane >> 4) & 1) * 16;
    const uint32_t aBaseH = smem_u32(sm) + AH_OFF + aRow * APITCH + aCol;
    const uint32_t aBaseL = smem_u32(sm) + AL_OFF + aRow * APITCH + aCol;
    const int bRow = n0w + ((lane >> 4) & 1) * 8 + (lane & 7);
    const int bCol = ((lane >> 3) & 1) * 16;
    const uint32_t bBaseH = smem_u32(sm) + BH_OFF + bRow * BPITCH + bCol;
    const uint32_t bBaseL = smem_u32(sm) + BL_OFF + bRow * BPITCH + bCol;

    float acc[2][8][4];
    #pragma unroll
    for (int mf = 0; mf < 2; mf++)
        #pragma unroll
        for (int nf = 0; nf < 8; nf++)
            #pragma unroll
            for (int q = 0; q < 4; q++) acc[mf][nf][q] = 0.0f;

    {
        float4 av[2];
        #pragma unroll
        for (int j = 0; j < 2; j++) av[j] = *reinterpret_cast<const float4*>(aSrc[j]);
        #pragma unroll
        for (int j = 0; j < 8; j++) cp16(bDst[j], bSrc[j]);
        cp_commit();
        #pragma unroll
        for (int j = 0; j < 2; j++) {
            float4 v = av[j];
            __nv_bfloat162 h01 = __floats2bfloat162_rn(v.x, v.y);
            __nv_bfloat162 h23 = __floats2bfloat162_rn(v.z, v.w);
            float2 f01 = __bfloat1622float2(h01);
            float2 f23 = __bfloat1622float2(h23);
            __nv_bfloat162 l01 = __floats2bfloat162_rn(v.x - f01.x, v.y - f01.y);
            __nv_bfloat162 l23 = __floats2bfloat162_rn(v.z - f23.x, v.w - f23.y);
            sts64(aHiDst[j], *reinterpret_cast<uint32_t*>(&h01),
                             *reinterpret_cast<uint32_t*>(&h23));
            sts64(aLoDst[j], *reinterpret_cast<uint32_t*>(&l01),
                             *reinterpret_cast<uint32_t*>(&l23));
        }
        cp_wait0();
        __syncthreads();
    }

    for (int t = 0; t < NCHUNK; t++) {
        const int cur = t & 1, nxt = cur ^ 1;
        const bool more = (t + 1 < NCHUNK);
        float4 av[2];
        if (more) {
            #pragma unroll
            for (int j = 0; j < 2; j++)
                av[j] = *reinterpret_cast<const float4*>(aSrc[j] + (size_t)(t + 1) * KC);
            #pragma unroll
            for (int j = 0; j < 8; j++)
                cp16(bDst[j] + nxt * STG, bSrc[j] + (size_t)(t + 1) * KC);
            cp_commit();
        }

        const uint32_t soff = cur * STG;
        #pragma unroll
        for (int j16 = 0; j16 < 2; j16++) {
            const int kb = j16 * 32;
            uint32_t ah[2][4], al[2][4];
            ldsm4(ah[0], aBaseH + soff + kb);
            ldsm4(ah[1], aBaseH + soff + 16 * APITCH + kb);
            ldsm4(al[0], aBaseL + soff + kb);
            ldsm4(al[1], aBaseL + soff + 16 * APITCH + kb);
            #pragma unroll
            for (int np = 0; np < 4; np++) {
                uint32_t bh[4], bl[4];
                ldsm4(bh, bBaseH + soff + np * 16 * BPITCH + kb);
                ldsm4(bl, bBaseL + soff + np * 16 * BPITCH + kb);
                #pragma unroll
                for (int h = 0; h < 2; h++) {
                    const int nf = 2 * np + h;
                    uint32_t b0h = bh[2 * h], b1h = bh[2 * h + 1];
                    uint32_t b0l = bl[2 * h], b1l = bl[2 * h + 1];
                    #pragma unroll
                    for (int mf = 0; mf < 2; mf++) {
                        mma16816(acc[mf][nf], ah[mf], b0h, b1h);
                        mma16816(acc[mf][nf], al[mf], b0h, b1h);
                        mma16816(acc[mf][nf], ah[mf], b0l, b1l);
                    }
                }
            }
        }

        if (more) {
            #pragma unroll
            for (int j = 0; j < 2; j++) {
                float4 v = av[j];
                __nv_bfloat162 h01 = __floats2bfloat162_rn(v.x, v.y);
                __nv_bfloat162 h23 = __floats2bfloat162_rn(v.z, v.w);
                float2 f01 = __bfloat1622float2(h01);
                float2 f23 = __bfloat1622float2(h23);
                __nv_bfloat162 l01 = __floats2bfloat162_rn(v.x - f01.x, v.y - f01.y);
                __nv_bfloat162 l23 = __floats2bfloat162_rn(v.z - f23.x, v.w - f23.y);
                sts64(aHiDst[j] + nxt * STG, *reinterpret_cast<uint32_t*>(&h01),
                                             *reinterpret_cast<uint32_t*>(&h23));
                sts64(aLoDst[j] + nxt * STG, *reinterpret_cast<uint32_t*>(&l01),
                                             *reinterpret_cast<uint32_t*>(&l23));
            }
        }
        cp_wait0();
        __syncthreads();
    }

    float* Mout = g_M + (size_t)p * NROWS * DDIM + (size_t)bx * 64 * DDIM;
    #pragma unroll
    for (int mf = 0; mf < 2; mf++) {
        #pragma unroll
        for (int nf = 0; nf < 8; nf++) {
            int r = m0w + mf * 16 + g;
            int c = n0w + nf * 8 + 2 * t4;
            *reinterpret_cast<float2*>(Mout + (size_t)r * DDIM + c) =
                make_float2(acc[mf][nf][0], acc[mf][nf][1]);
            *reinterpret_cast<float2*>(Mout + (size_t)(r + 8) * DDIM + c) =
                make_float2(acc[mf][nf][2], acc[mf][nf][3]);
        }
    }
}

// ===== fused epilogue GEMM: out = relu([X|S1|S2] @ Wc + bias), N-split =====
// A-producer computes T rows on the fly from X and g_M (region = k>>8,
// warp-uniform: regions are 256-aligned, BK=16 divides 256).
#define BM 64
#define BN 256
#define BNT 128
#define BK 16
#define THREADS 256

__device__ __forceinline__ float4 loadT(const float* __restrict__ X, int row, int k) {
    const int kk = k & 255;
    const size_t off = (size_t)row * DDIM + kk;
    const int region = k >> 8;
    if (region == 0) return *reinterpret_cast<const float4*>(X + off);
    float4 m0 = *reinterpret_cast<const float4*>(g_M + off);
    float4 m1 = *reinterpret_cast<const float4*>(g_M + (size_t)NROWS * DDIM + off);
    float4 m2 = *reinterpret_cast<const float4*>(g_M + 2 * (size_t)NROWS * DDIM + off);
    float4 s1;
    s1.x = m0.x + m1.x + m2.x;  s1.y = m0.y + m1.y + m2.y;
    s1.z = m0.z + m1.z + m2.z;  s1.w = m0.w + m1.w + m2.w;
    if (region == 1) return s1;
    float4 s2;
    s2.x = 0.5f * (s1.x * s1.x + m0.x * m0.x + m1.x * m1.x + m2.x * m2.x);
    s2.y = 0.5f * (s1.y * s1.y + m0.y * m0.y + m1.y * m1.y + m2.y * m2.y);
    s2.z = 0.5f * (s1.z * s1.z + m0.z * m0.z + m1.z * m1.z + m2.z * m2.z);
    s2.w = 0.5f * (s1.w * s1.w + m0.w * m0.w + m1.w * m1.w + m2.w * m2.w);
    return s2;
}

__global__ void __launch_bounds__(THREADS, 2)
gemm_epi_kernel(const float* __restrict__ X, const float* __restrict__ Bop,
                float* __restrict__ C)
{
    __shared__ __align__(16) float As[2][BK][BM + 4];
    __shared__ __align__(16) float Bs[2][BK][BNT];

    const int tid = threadIdx.x;
    const int nOff = blockIdx.x * BNT;
    const int K = 3 * DDIM;
    float* Cp = C + (long long)blockIdx.y * BM * DDIM + nOff;

    const int ar  = tid >> 2;                 // T row within tile
    const int akq = tid & 3;                  // k quad
    const int aRow = blockIdx.y * BM + ar;    // global T row
    const int tx = tid & 31;
    const int ty = tid >> 5;
    const int T = K / BK;                     // 48

    unsigned long long acc[8][2];
    #pragma unroll
    for (int i = 0; i < 8; i++) { acc[i][0] = 0ull; acc[i][1] = 0ull; }

    {
        #pragma unroll
        for (int q = 0; q < 2; q++) {
            int id = tid + THREADS * q;
            int row = id >> 5, c4 = id & 31;
            cp16(smem_u32(&Bs[0][row][c4 * 4]), Bop + (long long)row * BN + nOff + c4 * 4);
        }
        cp_commit();
        float4 a = loadT(X, aRow, akq * 4);
        As[0][4 * akq + 0][ar] = a.x; As[0][4 * akq + 1][ar] = a.y;
        As[0][4 * akq + 2][ar] = a.z; As[0][4 * akq + 3][ar] = a.w;
        cp_wait0();
        __syncthreads();
    }

    for (int t = 0; t < T; t++) {
        const int cur = t & 1, nxt = cur ^ 1;
        const bool more = (t + 1 < T);
        float4 aN;
        if (more) {
            aN = loadT(X, aRow, (t + 1) * BK + akq * 4);
            #pragma unroll
            for (int q = 0; q < 2; q++) {
                int id = tid + THREADS * q;
                int row = id >> 5, c4 = id & 31;
                cp16(smem_u32(&Bs[nxt][row][c4 * 4]),
                     Bop + (long long)((t + 1) * BK + row) * BN + nOff + c4 * 4);
            }
            cp_commit();
        }
        #pragma unroll
        for (int k = 0; k < BK; k++) {
            float4 a0 = *reinterpret_cast<const float4*>(&As[cur][k][ty * 8]);
            float4 a1 = *reinterpret_cast<const float4*>(&As[cur][k][ty * 8 + 4]);
            ulonglong2 bq0 = *reinterpret_cast<const ulonglong2*>(&Bs[cur][k][tx * 4]);
            unsigned long long bb[2] = {bq0.x, bq0.y};
            float av[8] = {a0.x, a0.y, a0.z, a0.w, a1.x, a1.y, a1.z, a1.w};
            #pragma unroll
            for (int i = 0; i < 8; i++) {
                unsigned long long a2 = pack2(av[i]);
                ffma2(acc[i][0], a2, bb[0]);
                ffma2(acc[i][1], a2, bb[1]);
            }
        }
        if (more) {
            cp_wait0();
            As[nxt][4 * akq + 0][ar] = aN.x; As[nxt][4 * akq + 1][ar] = aN.y;
            As[nxt][4 * akq + 2][ar] = aN.z; As[nxt][4 * akq + 3][ar] = aN.w;
        }
        __syncthreads();
    }

    float4 bias0 = *reinterpret_cast<const float4*>(&g_bias[nOff + tx * 4]);
    #pragma unroll
    for (int i = 0; i < 8; i++) {
        float2 p0 = unpack2(acc[i][0]);
        float2 p1 = unpack2(acc[i][1]);
        float4 v0 = make_float4(p0.x, p0.y, p1.x, p1.y);
        v0.x = fmaxf(v0.x + bias0.x, 0.0f); v0.y = fmaxf(v0.y + bias0.y, 0.0f);
        v0.z = fmaxf(v0.z + bias0.z, 0.0f); v0.w = fmaxf(v0.w + bias0.w, 0.0f);
        *reinterpret_cast<float4*>(Cp + (long long)(ty * 8 + i) * DDIM + tx * 4) = v0;
    }
}

// =============== launch ===============
extern "C" void kernel_launch(void* const* d_in, const int* in_sizes, int n_in,
                              void* d_out, int out_size) {
    const float *X = nullptr, *A = nullptr, *W = nullptr, *b = nullptr;
    for (int i = 0; i < n_in; i++) {
        long long s = in_sizes[i];
        if      (s == (long long)PP * NROWS * NROWS) A = (const float*)d_in[i];
        else if (s == (long long)NROWS * DDIM)       X = (const float*)d_in[i];
        else if (s == (long long)PP * DDIM * DDIM)   W = (const float*)d_in[i];
        else if (s == (long long)PP * DDIM)          b = (const float*)d_in[i];
    }
    float* pWc = nullptr;
    cudaGetSymbolAddress((void**)&pWc, g_Wc);

    cudaFuncSetAttribute(gemm1_kernel,
                         cudaFuncAttributeMaxDynamicSharedMemorySize, G1_SMEM);

    prep_kernel<<<(3 * DDIM * DDIM + 255) / 256, 256>>>(W, b);
    xt_kernel<<<dim3(NROWS / 32, DDIM / 32), dim3(32, 8)>>>(X);
    gemm1_kernel<<<dim3(NROWS / 64, PP), 256, G1_SMEM>>>(A);
    gemm_epi_kernel<<<dim3(2, NROWS / 64), THREADS>>>(X, pWc, (float*)d_out);
}

// round 13
// speedup vs baseline: 1.2214x; 1.0227x over previous
#include <cuda_runtime.h>
#include <cuda_bf16.h>
#include <cstdint>

#define NROWS 8192
#define DDIM  256
#define PP    3
#define KC    32
#define NCHUNK (NROWS / KC)      // 256
#define KEPI   (3 * DDIM)        // 768
#define NCHUNK_E (KEPI / KC)     // 24

// smem layout (per stage), 80B-padded rows  (shared by gemm1 and epi)
#define APITCH 80
#define BPITCH 80
#define AH_OFF 0
#define AL_OFF 5120
#define BH_OFF 10240
#define BL_OFF 30720
#define STG    51200
#define G1_SMEM (2 * STG)        // 102400

// ---- scratch (device globals; no allocation allowed) ----
__device__ __align__(16) float g_M[PP * NROWS * DDIM];
__device__ __align__(16) float g_bias[DDIM];
__device__ __align__(16) __nv_bfloat16 g_Xth[DDIM * NROWS];   // X^T hi  [d][k]
__device__ __align__(16) __nv_bfloat16 g_Xtl[DDIM * NROWS];   // X^T lo  [d][k]
__device__ __align__(16) __nv_bfloat16 g_Wbh[DDIM * KEPI];    // W as B[n][k] hi
__device__ __align__(16) __nv_bfloat16 g_Wbl[DDIM * KEPI];    // W as B[n][k] lo

// =============== helpers ===============
__device__ __forceinline__ unsigned smem_u32(const void* p) {
    return (unsigned)__cvta_generic_to_shared(p);
}
__device__ __forceinline__ void cp16(unsigned dst, const void* src) {
    asm volatile("cp.async.cg.shared.global [%0], [%1], 16;" :: "r"(dst), "l"(src));
}
__device__ __forceinline__ void cp_commit() { asm volatile("cp.async.commit_group;"); }
__device__ __forceinline__ void cp_wait0()  { asm volatile("cp.async.wait_group 0;"); }

__device__ __forceinline__ void sts64(uint32_t addr, uint32_t v0, uint32_t v1) {
    asm volatile("st.shared.v2.b32 [%0], {%1, %2};" :: "r"(addr), "r"(v0), "r"(v1) : "memory");
}

// ldmatrix x4 (sm_75+, legal at plain sm_103)
__device__ __forceinline__ void ldsm4(uint32_t* r, uint32_t addr) {
    asm volatile("ldmatrix.sync.aligned.m8n8.x4.shared.b16 {%0,%1,%2,%3}, [%4];"
                 : "=r"(r[0]), "=r"(r[1]), "=r"(r[2]), "=r"(r[3]) : "r"(addr));
}

// HMMA m16n8k16 bf16
__device__ __forceinline__ void mma16816(float* c, const uint32_t* a,
                                         uint32_t b0, uint32_t b1) {
    asm("mma.sync.aligned.m16n8k16.row.col.f32.bf16.bf16.f32 "
        "{%0,%1,%2,%3}, {%4,%5,%6,%7}, {%8,%9}, {%0,%1,%2,%3};"
        : "+f"(c[0]), "+f"(c[1]), "+f"(c[2]), "+f"(c[3])
        : "r"(a[0]), "r"(a[1]), "r"(a[2]), "r"(a[3]), "r"(b0), "r"(b1));
}

__device__ __forceinline__ void split_sts(uint32_t hiAddr, uint32_t loAddr, float4 v) {
    __nv_bfloat162 h01 = __floats2bfloat162_rn(v.x, v.y);
    __nv_bfloat162 h23 = __floats2bfloat162_rn(v.z, v.w);
    float2 f01 = __bfloat1622float2(h01);
    float2 f23 = __bfloat1622float2(h23);
    __nv_bfloat162 l01 = __floats2bfloat162_rn(v.x - f01.x, v.y - f01.y);
    __nv_bfloat162 l23 = __floats2bfloat162_rn(v.z - f23.x, v.w - f23.y);
    sts64(hiAddr, *reinterpret_cast<uint32_t*>(&h01), *reinterpret_cast<uint32_t*>(&h23));
    sts64(loAddr, *reinterpret_cast<uint32_t*>(&l01), *reinterpret_cast<uint32_t*>(&l23));
}

// =============== X^T transpose + bf16 hi/lo split ===============
__global__ void xt_kernel(const float* __restrict__ X) {
    __shared__ float tile[32][33];
    int k0 = blockIdx.x * 32, d0 = blockIdx.y * 32;
    int tx = threadIdx.x, ty = threadIdx.y;     // 32 x 8
    #pragma unroll
    for (int i = 0; i < 4; i++)
        tile[ty + 8 * i][tx] = X[(size_t)(k0 + ty + 8 * i) * DDIM + d0 + tx];
    __syncthreads();
    #pragma unroll
    for (int i = 0; i < 4; i++) {
        int d = d0 + ty + 8 * i, k = k0 + tx;
        float v = tile[tx][ty + 8 * i];
        __nv_bfloat16 h = __float2bfloat16(v);
        __nv_bfloat16 l = __float2bfloat16(v - __bfloat162float(h));
        g_Xth[(size_t)d * NROWS + k] = h;
        g_Xtl[(size_t)d * NROWS + k] = l;
    }
}

// =============== prep: W -> B[n][k] bf16 hi/lo + fused bias ===============
__global__ void prep_kernel(const float* __restrict__ W, const float* __restrict__ b) {
    int idx = blockIdx.x * blockDim.x + threadIdx.x;
    if (idx < 3 * DDIM * DDIM) {
        int kk = idx & (DDIM - 1);
        int rd = idx >> 8;
        int d  = rd & (DDIM - 1);
        int r  = rd >> 8;
        float v = W[idx];
        __nv_bfloat16 h = __float2bfloat16(v);
        __nv_bfloat16 l = __float2bfloat16(v - __bfloat162float(h));
        int k = r * DDIM + kk;
        g_Wbh[d * KEPI + k] = h;
        g_Wbl[d * KEPI + k] = l;
    }
    if (idx < DDIM)
        g_bias[idx] = b[idx] + 3.0f * b[DDIM + idx] + 6.0f * b[2 * DDIM + idx];
}

// =============== gemm1: M_p = A_p @ X  (HMMA bf16 3-term split) — R9 exact =====
__global__ __launch_bounds__(256, 2)
void gemm1_kernel(const float* __restrict__ A) {
    extern __shared__ char sm[];

    const int tid  = threadIdx.x;
    const int wid  = tid >> 5;
    const int lane = tid & 31;
    const int g    = lane >> 2;
    const int t4   = lane & 3;
    const int m0w  = (wid >> 2) * 32;
    const int n0w  = (wid & 3) * 64;
    const int bx = blockIdx.x, p = blockIdx.y;

    const float* Ap = A + (size_t)p * NROWS * NROWS + (size_t)bx * 64 * NROWS;

    const float* aSrc[2];
    uint32_t aHiDst[2], aLoDst[2];
    #pragma unroll
    for (int j = 0; j < 2; j++) {
        int idx = j * 256 + tid;
        int r = idx >> 3, c = idx & 7;
        aSrc[j]  = Ap + (size_t)r * NROWS + c * 4;
        aHiDst[j] = smem_u32(sm) + AH_OFF + r * APITCH + c * 8;
        aLoDst[j] = smem_u32(sm) + AL_OFF + r * APITCH + c * 8;
    }
    const __nv_bfloat16* bSrc[8];
    uint32_t bDst[8];
    #pragma unroll
    for (int j = 0; j < 8; j++) {
        int idx = j * 256 + tid;
        int half = idx >> 10;
        int q = idx & 1023;
        int n = q >> 2, c = q & 3;
        bSrc[j] = (half ? g_Xtl : g_Xth) + (size_t)n * NROWS + c * 8;
        bDst[j] = smem_u32(sm) + (half ? BL_OFF : BH_OFF) + n * BPITCH + c * 16;
    }

    const int aRow = m0w + (lane & 7) + ((lane >> 3) & 1) * 8;
    const int aCol = ((lane >> 4) & 1) * 16;
    const uint32_t aBaseH = smem_u32(sm) + AH_OFF + aRow * APITCH + aCol;
    const uint32_t aBaseL = smem_u32(sm) + AL_OFF + aRow * APITCH + aCol;
    const int bRow = n0w + ((lane >> 4) & 1) * 8 + (lane & 7);
    const int bCol = ((lane >> 3) & 1) * 16;
    const uint32_t bBaseH = smem_u32(sm) + BH_OFF + bRow * BPITCH + bCol;
    const uint32_t bBaseL = smem_u32(sm) + BL_OFF + bRow * BPITCH + bCol;

    float acc[2][8][4];
    #pragma unroll
    for (int mf = 0; mf < 2; mf++)
        #pragma unroll
        for (int nf = 0; nf < 8; nf++)
            #pragma unroll
            for (int q = 0; q < 4; q++) acc[mf][nf][q] = 0.0f;

    {
        float4 av[2];
        #pragma unroll
        for (int j = 0; j < 2; j++) av[j] = *reinterpret_cast<const float4*>(aSrc[j]);
        #pragma unroll
        for (int j = 0; j < 8; j++) cp16(bDst[j], bSrc[j]);
        cp_commit();
        #pragma unroll
        for (int j = 0; j < 2; j++) split_sts(aHiDst[j], aLoDst[j], av[j]);
        cp_wait0();
        __syncthreads();
    }

    for (int t = 0; t < NCHUNK; t++) {
        const int cur = t & 1, nxt = cur ^ 1;
        const bool more = (t + 1 < NCHUNK);
        float4 av[2];
        if (more) {
            #pragma unroll
            for (int j = 0; j < 2; j++)
                av[j] = *reinterpret_cast<const float4*>(aSrc[j] + (size_t)(t + 1) * KC);
            #pragma unroll
            for (int j = 0; j < 8; j++)
                cp16(bDst[j] + nxt * STG, bSrc[j] + (size_t)(t + 1) * KC);
            cp_commit();
        }

        const uint32_t soff = cur * STG;
        #pragma unroll
        for (int j16 = 0; j16 < 2; j16++) {
            const int kb = j16 * 32;
            uint32_t ah[2][4], al[2][4];
            ldsm4(ah[0], aBaseH + soff + kb);
            ldsm4(ah[1], aBaseH + soff + 16 * APITCH + kb);
            ldsm4(al[0], aBaseL + soff + kb);
            ldsm4(al[1], aBaseL + soff + 16 * APITCH + kb);
            #pragma unroll
            for (int np = 0; np < 4; np++) {
                uint32_t bh[4], bl[4];
                ldsm4(bh, bBaseH + soff + np * 16 * BPITCH + kb);
                ldsm4(bl, bBaseL + soff + np * 16 * BPITCH + kb);
                #pragma unroll
                for (int h = 0; h < 2; h++) {
                    const int nf = 2 * np + h;
                    uint32_t b0h = bh[2 * h], b1h = bh[2 * h + 1];
                    uint32_t b0l = bl[2 * h], b1l = bl[2 * h + 1];
                    #pragma unroll
                    for (int mf = 0; mf < 2; mf++) {
                        mma16816(acc[mf][nf], ah[mf], b0h, b1h);
                        mma16816(acc[mf][nf], al[mf], b0h, b1h);
                        mma16816(acc[mf][nf], ah[mf], b0l, b1l);
                    }
                }
            }
        }

        if (more) {
            #pragma unroll
            for (int j = 0; j < 2; j++)
                split_sts(aHiDst[j] + nxt * STG, aLoDst[j] + nxt * STG, av[j]);
        }
        cp_wait0();
        __syncthreads();
    }

    float* Mout = g_M + (size_t)p * NROWS * DDIM + (size_t)bx * 64 * DDIM;
    #pragma unroll
    for (int mf = 0; mf < 2; mf++) {
        #pragma unroll
        for (int nf = 0; nf < 8; nf++) {
            int r = m0w + mf * 16 + g;
            int c = n0w + nf * 8 + 2 * t4;
            *reinterpret_cast<float2*>(Mout + (size_t)r * DDIM + c) =
                make_float2(acc[mf][nf][0], acc[mf][nf][1]);
            *reinterpret_cast<float2*>(Mout + (size_t)(r + 8) * DDIM + c) =
                make_float2(acc[mf][nf][2], acc[mf][nf][3]);
        }
    }
}

// ===== T row compute on the fly: region = k>>8, uniform per chunk =====
__device__ __forceinline__ float4 loadT(const float* __restrict__ X, int row, int k) {
    const int kk = k & 255;
    const size_t off = (size_t)row * DDIM + kk;
    const int region = k >> 8;
    if (region == 0) return *reinterpret_cast<const float4*>(X + off);
    float4 m0 = *reinterpret_cast<const float4*>(g_M + off);
    float4 m1 = *reinterpret_cast<const float4*>(g_M + (size_t)NROWS * DDIM + off);
    float4 m2 = *reinterpret_cast<const float4*>(g_M + 2 * (size_t)NROWS * DDIM + off);
    float4 s1;
    s1.x = m0.x + m1.x + m2.x;  s1.y = m0.y + m1.y + m2.y;
    s1.z = m0.z + m1.z + m2.z;  s1.w = m0.w + m1.w + m2.w;
    if (region == 1) return s1;
    float4 s2;
    s2.x = 0.5f * (s1.x * s1.x + m0.x * m0.x + m1.x * m1.x + m2.x * m2.x);
    s2.y = 0.5f * (s1.y * s1.y + m0.y * m0.y + m1.y * m1.y + m2.y * m2.y);
    s2.z = 0.5f * (s1.z * s1.z + m0.z * m0.z + m1.z * m1.z + m2.z * m2.z);
    s2.w = 0.5f * (s1.w * s1.w + m0.w * m0.w + m1.w * m1.w + m2.w * m2.w);
    return s2;
}

// ===== epilogue GEMM (HMMA): out = relu(T @ W^T + bias) ======================
// Same structure as gemm1: CTA 64x256, BK=32, NCHUNK_E=24, B = g_Wb (stride 768).
__global__ __launch_bounds__(256, 2)
void gemm_epi_kernel(const float* __restrict__ X, float* __restrict__ C) {
    extern __shared__ char sm[];

    const int tid  = threadIdx.x;
    const int wid  = tid >> 5;
    const int lane = tid & 31;
    const int g    = lane >> 2;
    const int t4   = lane & 3;
    const int m0w  = (wid >> 2) * 32;
    const int n0w  = (wid & 3) * 64;
    const int bx = blockIdx.x;

    int aRowG[2];                 // global T rows for producer
    uint32_t aHiDst[2], aLoDst[2];
    int aColK[2];
    #pragma unroll
    for (int j = 0; j < 2; j++) {
        int idx = j * 256 + tid;
        int r = idx >> 3, c = idx & 7;
        aRowG[j] = bx * 64 + r;
        aColK[j] = c * 4;
        aHiDst[j] = smem_u32(sm) + AH_OFF + r * APITCH + c * 8;
        aLoDst[j] = smem_u32(sm) + AL_OFF + r * APITCH + c * 8;
    }
    const __nv_bfloat16* bSrc[8];
    uint32_t bDst[8];
    #pragma unroll
    for (int j = 0; j < 8; j++) {
        int idx = j * 256 + tid;
        int half = idx >> 10;
        int q = idx & 1023;
        int n = q >> 2, c = q & 3;
        bSrc[j] = (half ? g_Wbl : g_Wbh) + (size_t)n * KEPI + c * 8;
        bDst[j] = smem_u32(sm) + (half ? BL_OFF : BH_OFF) + n * BPITCH + c * 16;
    }

    const int aRow = m0w + (lane & 7) + ((lane >> 3) & 1) * 8;
    const int aCol = ((lane >> 4) & 1) * 16;
    const uint32_t aBaseH = smem_u32(sm) + AH_OFF + aRow * APITCH + aCol;
    const uint32_t aBaseL = smem_u32(sm) + AL_OFF + aRow * APITCH + aCol;
    const int bRow = n0w + ((lane >> 4) & 1) * 8 + (lane & 7);
    const int bCol = ((lane >> 3) & 1) * 16;
    const uint32_t bBaseH = smem_u32(sm) + BH_OFF + bRow * BPITCH + bCol;
    const uint32_t bBaseL = smem_u32(sm) + BL_OFF + bRow * BPITCH + bCol;

    float acc[2][8][4];
    #pragma unroll
    for (int mf = 0; mf < 2; mf++)
        #pragma unroll
        for (int nf = 0; nf < 8; nf++)
            #pragma unroll
            for (int q = 0; q < 4; q++) acc[mf][nf][q] = 0.0f;

    {
        float4 av[2];
        #pragma unroll
        for (int j = 0; j < 2; j++) av[j] = loadT(X, aRowG[j], aColK[j]);
        #pragma unroll
        for (int j = 0; j < 8; j++) cp16(bDst[j], bSrc[j]);
        cp_commit();
        #pragma unroll
        for (int j = 0; j < 2; j++) split_sts(aHiDst[j], aLoDst[j], av[j]);
        cp_wait0();
        __syncthreads();
    }

    for (int t = 0; t < NCHUNK_E; t++) {
        const int cur = t & 1, nxt = cur ^ 1;
        const bool more = (t + 1 < NCHUNK_E);
        float4 av[2];
        if (more) {
            #pragma unroll
            for (int j = 0; j < 2; j++)
                av[j] = loadT(X, aRowG[j], (t + 1) * KC + aColK[j]);
            #pragma unroll
            for (int j = 0; j < 8; j++)
                cp16(bDst[j] + nxt * STG, bSrc[j] + (size_t)(t + 1) * KC);
            cp_commit();
        }

        const uint32_t soff = cur * STG;
        #pragma unroll
        for (int j16 = 0; j16 < 2; j16++) {
            const int kb = j16 * 32;
            uint32_t ah[2][4], al[2][4];
            ldsm4(ah[0], aBaseH + soff + kb);
            ldsm4(ah[1], aBaseH + soff + 16 * APITCH + kb);
            ldsm4(al[0], aBaseL + soff + kb);
            ldsm4(al[1], aBaseL + soff + 16 * APITCH + kb);
            #pragma unroll
            for (int np = 0; np < 4; np++) {
                uint32_t bh[4], bl[4];
                ldsm4(bh, bBaseH + soff + np * 16 * BPITCH + kb);
                ldsm4(bl, bBaseL + soff + np * 16 * BPITCH + kb);
                #pragma unroll
                for (int h = 0; h < 2; h++) {
                    const int nf = 2 * np + h;
                    uint32_t b0h = bh[2 * h], b1h = bh[2 * h + 1];
                    uint32_t b0l = bl[2 * h], b1l = bl[2 * h + 1];
                    #pragma unroll
                    for (int mf = 0; mf < 2; mf++) {
                        mma16816(acc[mf][nf], ah[mf], b0h, b1h);
                        mma16816(acc[mf][nf], al[mf], b0h, b1h);
                        mma16816(acc[mf][nf], ah[mf], b0l, b1l);
                    }
                }
            }
        }

        if (more) {
            #pragma unroll
            for (int j = 0; j < 2; j++)
                split_sts(aHiDst[j] + nxt * STG, aLoDst[j] + nxt * STG, av[j]);
        }
        cp_wait0();
        __syncthreads();
    }

    float* Cp = C + (size_t)(bx * 64) * DDIM;
    #pragma unroll
    for (int mf = 0; mf < 2; mf++) {
        #pragma unroll
        for (int nf = 0; nf < 8; nf++) {
            int r = m0w + mf * 16 + g;
            int c = n0w + nf * 8 + 2 * t4;
            float2 bias = *reinterpret_cast<const float2*>(g_bias + c);
            float2 v0 = make_float2(fmaxf(acc[mf][nf][0] + bias.x, 0.0f),
                                    fmaxf(acc[mf][nf][1] + bias.y, 0.0f));
            float2 v1 = make_float2(fmaxf(acc[mf][nf][2] + bias.x, 0.0f),
                                    fmaxf(acc[mf][nf][3] + bias.y, 0.0f));
            *reinterpret_cast<float2*>(Cp + (size_t)r * DDIM + c)       = v0;
            *reinterpret_cast<float2*>(Cp + (size_t)(r + 8) * DDIM + c) = v1;
        }
    }
}

// =============== launch ===============
extern "C" void kernel_launch(void* const* d_in, const int* in_sizes, int n_in,
                              void* d_out, int out_size) {
    const float *X = nullptr, *A = nullptr, *W = nullptr, *b = nullptr;
    for (int i = 0; i < n_in; i++) {
        long long s = in_sizes[i];
        if      (s == (long long)PP * NROWS * NROWS) A = (const float*)d_in[i];
        else if (s == (long long)NROWS * DDIM)       X = (const float*)d_in[i];
        else if (s == (long long)PP * DDIM * DDIM)   W = (const float*)d_in[i];
        else if (s == (long long)PP * DDIM)          b = (const float*)d_in[i];
    }
    cudaFuncSetAttribute(gemm1_kernel,
                         cudaFuncAttributeMaxDynamicSharedMemorySize, G1_SMEM);
    cudaFuncSetAttribute(gemm_epi_kernel,
                         cudaFuncAttributeMaxDynamicSharedMemorySize, G1_SMEM);

    prep_kernel<<<(3 * DDIM * DDIM + 255) / 256, 256>>>(W, b);
    xt_kernel<<<dim3(NROWS / 32, DDIM / 32), dim3(32, 8)>>>(X);
    gemm1_kernel<<<dim3(NROWS / 64, PP), 256, G1_SMEM>>>(A);
    gemm_epi_kernel<<<NROWS / 64, 256, G1_SMEM>>>(X, (float*)d_out);
}

// round 14
// speedup vs baseline: 1.2356x; 1.0116x over previous
#include <cuda_runtime.h>
#include <cuda_bf16.h>
#include <cstdint>

#define NROWS 8192
#define DDIM  256
#define PP    3
#define KC    32
#define NCHUNK (NROWS / KC)      // 256
#define KEPI   (3 * DDIM)        // 768
#define NCHUNK_E (KEPI / KC)     // 24

// gemm1 smem layout (per stage), 80B-padded rows
#define APITCH 80
#define BPITCH 80
#define AH_OFF 0
#define AL_OFF 5120
#define BH_OFF 10240
#define BL_OFF 30720
#define STG    51200
#define G1_SMEM (2 * STG)        // 102400

// epi smem layout (M=32 tiles)
#define EAH_OFF 0
#define EAL_OFF 2560
#define EBH_OFF 5120
#define EBL_OFF 25600
#define ESTG    46080
#define EPI_SMEM (2 * ESTG)      // 92160

// ---- scratch (device globals; no allocation allowed) ----
__device__ __align__(16) float g_M[PP * NROWS * DDIM];
__device__ __align__(16) float g_bias[DDIM];
__device__ __align__(16) __nv_bfloat16 g_Xth[DDIM * NROWS];   // X^T hi  [d][k]
__device__ __align__(16) __nv_bfloat16 g_Xtl[DDIM * NROWS];   // X^T lo  [d][k]
__device__ __align__(16) __nv_bfloat16 g_Wbh[DDIM * KEPI];    // W as B[n][k] hi
__device__ __align__(16) __nv_bfloat16 g_Wbl[DDIM * KEPI];    // W as B[n][k] lo

// =============== helpers ===============
__device__ __forceinline__ unsigned smem_u32(const void* p) {
    return (unsigned)__cvta_generic_to_shared(p);
}
__device__ __forceinline__ void cp16(unsigned dst, const void* src) {
    asm volatile("cp.async.cg.shared.global [%0], [%1], 16;" :: "r"(dst), "l"(src));
}
__device__ __forceinline__ void cp_commit() { asm volatile("cp.async.commit_group;"); }
__device__ __forceinline__ void cp_wait0()  { asm volatile("cp.async.wait_group 0;"); }

__device__ __forceinline__ void sts64(uint32_t addr, uint32_t v0, uint32_t v1) {
    asm volatile("st.shared.v2.b32 [%0], {%1, %2};" :: "r"(addr), "r"(v0), "r"(v1) : "memory");
}

// ldmatrix x4 (sm_75+, legal at plain sm_103)
__device__ __forceinline__ void ldsm4(uint32_t* r, uint32_t addr) {
    asm volatile("ldmatrix.sync.aligned.m8n8.x4.shared.b16 {%0,%1,%2,%3}, [%4];"
                 : "=r"(r[0]), "=r"(r[1]), "=r"(r[2]), "=r"(r[3]) : "r"(addr));
}

// HMMA m16n8k16 bf16
__device__ __forceinline__ void mma16816(float* c, const uint32_t* a,
                                         uint32_t b0, uint32_t b1) {
    asm("mma.sync.aligned.m16n8k16.row.col.f32.bf16.bf16.f32 "
        "{%0,%1,%2,%3}, {%4,%5,%6,%7}, {%8,%9}, {%0,%1,%2,%3};"
        : "+f"(c[0]), "+f"(c[1]), "+f"(c[2]), "+f"(c[3])
        : "r"(a[0]), "r"(a[1]), "r"(a[2]), "r"(a[3]), "r"(b0), "r"(b1));
}

__device__ __forceinline__ void split_sts(uint32_t hiAddr, uint32_t loAddr, float4 v) {
    __nv_bfloat162 h01 = __floats2bfloat162_rn(v.x, v.y);
    __nv_bfloat162 h23 = __floats2bfloat162_rn(v.z, v.w);
    float2 f01 = __bfloat1622float2(h01);
    float2 f23 = __bfloat1622float2(h23);
    __nv_bfloat162 l01 = __floats2bfloat162_rn(v.x - f01.x, v.y - f01.y);
    __nv_bfloat162 l23 = __floats2bfloat162_rn(v.z - f23.x, v.w - f23.y);
    sts64(hiAddr, *reinterpret_cast<uint32_t*>(&h01), *reinterpret_cast<uint32_t*>(&h23));
    sts64(loAddr, *reinterpret_cast<uint32_t*>(&l01), *reinterpret_cast<uint32_t*>(&l23));
}

// =============== X^T transpose + bf16 hi/lo split ===============
__global__ void xt_kernel(const float* __restrict__ X) {
    __shared__ float tile[32][33];
    int k0 = blockIdx.x * 32, d0 = blockIdx.y * 32;
    int tx = threadIdx.x, ty = threadIdx.y;     // 32 x 8
    #pragma unroll
    for (int i = 0; i < 4; i++)
        tile[ty + 8 * i][tx] = X[(size_t)(k0 + ty + 8 * i) * DDIM + d0 + tx];
    __syncthreads();
    #pragma unroll
    for (int i = 0; i < 4; i++) {
        int d = d0 + ty + 8 * i, k = k0 + tx;
        float v = tile[tx][ty + 8 * i];
        __nv_bfloat16 h = __float2bfloat16(v);
        __nv_bfloat16 l = __float2bfloat16(v - __bfloat162float(h));
        g_Xth[(size_t)d * NROWS + k] = h;
        g_Xtl[(size_t)d * NROWS + k] = l;
    }
}

// =============== prep: W -> B[n][k] bf16 hi/lo + fused bias ===============
__global__ void prep_kernel(const float* __restrict__ W, const float* __restrict__ b) {
    int idx = blockIdx.x * blockDim.x + threadIdx.x;
    if (idx < 3 * DDIM * DDIM) {
        int kk = idx & (DDIM - 1);
        int rd = idx >> 8;
        int d  = rd & (DDIM - 1);
        int r  = rd >> 8;
        float v = W[idx];
        __nv_bfloat16 h = __float2bfloat16(v);
        __nv_bfloat16 l = __float2bfloat16(v - __bfloat162float(h));
        int k = r * DDIM + kk;
        g_Wbh[d * KEPI + k] = h;
        g_Wbl[d * KEPI + k] = l;
    }
    if (idx < DDIM)
        g_bias[idx] = b[idx] + 3.0f * b[DDIM + idx] + 6.0f * b[2 * DDIM + idx];
}

// =============== gemm1: M_p = A_p @ X  (HMMA bf16 3-term split) — R9 exact =====
__global__ __launch_bounds__(256, 2)
void gemm1_kernel(const float* __restrict__ A) {
    extern __shared__ char sm[];

    const int tid  = threadIdx.x;
    const int wid  = tid >> 5;
    const int lane = tid & 31;
    const int g    = lane >> 2;
    const int t4   = lane & 3;
    const int m0w  = (wid >> 2) * 32;
    const int n0w  = (wid & 3) * 64;
    const int bx = blockIdx.x, p = blockIdx.y;

    const float* Ap = A + (size_t)p * NROWS * NROWS + (size_t)bx * 64 * NROWS;

    const float* aSrc[2];
    uint32_t aHiDst[2], aLoDst[2];
    #pragma unroll
    for (int j = 0; j < 2; j++) {
        int idx = j * 256 + tid;
        int r = idx >> 3, c = idx & 7;
        aSrc[j]  = Ap + (size_t)r * NROWS + c * 4;
        aHiDst[j] = smem_u32(sm) + AH_OFF + r * APITCH + c * 8;
        aLoDst[j] = smem_u32(sm) + AL_OFF + r * APITCH + c * 8;
    }
    const __nv_bfloat16* bSrc[8];
    uint32_t bDst[8];
    #pragma unroll
    for (int j = 0; j < 8; j++) {
        int idx = j * 256 + tid;
        int half = idx >> 10;
        int q = idx & 1023;
        int n = q >> 2, c = q & 3;
        bSrc[j] = (half ? g_Xtl : g_Xth) + (size_t)n * NROWS + c * 8;
        bDst[j] = smem_u32(sm) + (half ? BL_OFF : BH_OFF) + n * BPITCH + c * 16;
    }

    const int aRow = m0w + (lane & 7) + ((lane >> 3) & 1) * 8;
    const int aCol = ((lane >> 4) & 1) * 16;
    const uint32_t aBaseH = smem_u32(sm) + AH_OFF + aRow * APITCH + aCol;
    const uint32_t aBaseL = smem_u32(sm) + AL_OFF + aRow * APITCH + aCol;
    const int bRow = n0w + ((lane >> 4) & 1) * 8 + (lane & 7);
    const int bCol = ((lane >> 3) & 1) * 16;
    const uint32_t bBaseH = smem_u32(sm) + BH_OFF + bRow * BPITCH + bCol;
    const uint32_t bBaseL = smem_u32(sm) + BL_OFF + bRow * BPITCH + bCol;

    float acc[2][8][4];
    #pragma unroll
    for (int mf = 0; mf < 2; mf++)
        #pragma unroll
        for (int nf = 0; nf < 8; nf++)
            #pragma unroll
            for (int q = 0; q < 4; q++) acc[mf][nf][q] = 0.0f;

    {
        float4 av[2];
        #pragma unroll
        for (int j = 0; j < 2; j++) av[j] = *reinterpret_cast<const float4*>(aSrc[j]);
        #pragma unroll
        for (int j = 0; j < 8; j++) cp16(bDst[j], bSrc[j]);
        cp_commit();
        #pragma unroll
        for (int j = 0; j < 2; j++) split_sts(aHiDst[j], aLoDst[j], av[j]);
        cp_wait0();
        __syncthreads();
    }

    for (int t = 0; t < NCHUNK; t++) {
        const int cur = t & 1, nxt = cur ^ 1;
        const bool more = (t + 1 < NCHUNK);
        float4 av[2];
        if (more) {
            #pragma unroll
            for (int j = 0; j < 2; j++)
                av[j] = *reinterpret_cast<const float4*>(aSrc[j] + (size_t)(t + 1) * KC);
            #pragma unroll
            for (int j = 0; j < 8; j++)
                cp16(bDst[j] + nxt * STG, bSrc[j] + (size_t)(t + 1) * KC);
            cp_commit();
        }

        const uint32_t soff = cur * STG;
        #pragma unroll
        for (int j16 = 0; j16 < 2; j16++) {
            const int kb = j16 * 32;
            uint32_t ah[2][4], al[2][4];
            ldsm4(ah[0], aBaseH + soff + kb);
            ldsm4(ah[1], aBaseH + soff + 16 * APITCH + kb);
            ldsm4(al[0], aBaseL + soff + kb);
            ldsm4(al[1], aBaseL + soff + 16 * APITCH + kb);
            #pragma unroll
            for (int np = 0; np < 4; np++) {
                uint32_t bh[4], bl[4];
                ldsm4(bh, bBaseH + soff + np * 16 * BPITCH + kb);
                ldsm4(bl, bBaseL + soff + np * 16 * BPITCH + kb);
                #pragma unroll
                for (int h = 0; h < 2; h++) {
                    const int nf = 2 * np + h;
                    uint32_t b0h = bh[2 * h], b1h = bh[2 * h + 1];
                    uint32_t b0l = bl[2 * h], b1l = bl[2 * h + 1];
                    #pragma unroll
                    for (int mf = 0; mf < 2; mf++) {
                        mma16816(acc[mf][nf], ah[mf], b0h, b1h);
                        mma16816(acc[mf][nf], al[mf], b0h, b1h);
                        mma16816(acc[mf][nf], ah[mf], b0l, b1l);
                    }
                }
            }
        }

        if (more) {
            #pragma unroll
            for (int j = 0; j < 2; j++)
                split_sts(aHiDst[j] + nxt * STG, aLoDst[j] + nxt * STG, av[j]);
        }
        cp_wait0();
        __syncthreads();
    }

    float* Mout = g_M + (size_t)p * NROWS * DDIM + (size_t)bx * 64 * DDIM;
    #pragma unroll
    for (int mf = 0; mf < 2; mf++) {
        #pragma unroll
        for (int nf = 0; nf < 8; nf++) {
            int r = m0w + mf * 16 + g;
            int c = n0w + nf * 8 + 2 * t4;
            *reinterpret_cast<float2*>(Mout + (size_t)r * DDIM + c) =
                make_float2(acc[mf][nf][0], acc[mf][nf][1]);
            *reinterpret_cast<float2*>(Mout + (size_t)(r + 8) * DDIM + c) =
                make_float2(acc[mf][nf][2], acc[mf][nf][3]);
        }
    }
}

// ===== T row compute on the fly: region = k>>8, uniform per chunk =====
__device__ __forceinline__ float4 loadT(const float* __restrict__ X, int row, int k) {
    const int kk = k & 255;
    const size_t off = (size_t)row * DDIM + kk;
    const int region = k >> 8;
    if (region == 0) return *reinterpret_cast<const float4*>(X + off);
    float4 m0 = *reinterpret_cast<const float4*>(g_M + off);
    float4 m1 = *reinterpret_cast<const float4*>(g_M + (size_t)NROWS * DDIM + off);
    float4 m2 = *reinterpret_cast<const float4*>(g_M + 2 * (size_t)NROWS * DDIM + off);
    float4 s1;
    s1.x = m0.x + m1.x + m2.x;  s1.y = m0.y + m1.y + m2.y;
    s1.z = m0.z + m1.z + m2.z;  s1.w = m0.w + m1.w + m2.w;
    if (region == 1) return s1;
    float4 s2;
    s2.x = 0.5f * (s1.x * s1.x + m0.x * m0.x + m1.x * m1.x + m2.x * m2.x);
    s2.y = 0.5f * (s1.y * s1.y + m0.y * m0.y + m1.y * m1.y + m2.y * m2.y);
    s2.z = 0.5f * (s1.z * s1.z + m0.z * m0.z + m1.z * m1.z + m2.z * m2.z);
    s2.w = 0.5f * (s1.w * s1.w + m0.w * m0.w + m1.w * m1.w + m2.w * m2.w);
    return s2;
}

// ===== epilogue GEMM (HMMA): out = relu(T @ W^T + bias), M=32 tiles ===========
// CTA 32x256, BK=32, 256 threads, 8 warps (2 m-groups x 4 n-groups),
// warp tile 16x64 (1 m16-frag x 8 n8-frags). Grid 256 CTAs, 2/SM.
__global__ __launch_bounds__(256, 2)
void gemm_epi_kernel(const float* __restrict__ X, float* __restrict__ C) {
    extern __shared__ char sm[];

    const int tid  = threadIdx.x;
    const int wid  = tid >> 5;
    const int lane = tid & 31;
    const int g    = lane >> 2;
    const int t4   = lane & 3;
    const int m0w  = (wid >> 2) * 16;     // 0 or 16
    const int n0w  = (wid & 3) * 64;
    const int bx = blockIdx.x;

    // producer A: 32 rows x 8 float4 = 256 -> 1 per thread
    const int arw = tid >> 3, acl = tid & 7;
    const int aRowG = bx * 32 + arw;
    const uint32_t aHiDst = smem_u32(sm) + EAH_OFF + arw * APITCH + acl * 8;
    const uint32_t aLoDst = smem_u32(sm) + EAL_OFF + arw * APITCH + acl * 8;
    // producer B: 2048 cp16 -> 8 per thread
    const __nv_bfloat16* bSrc[8];
    uint32_t bDst[8];
    #pragma unroll
    for (int j = 0; j < 8; j++) {
        int idx = j * 256 + tid;
        int half = idx >> 10;
        int q = idx & 1023;
        int n = q >> 2, c = q & 3;
        bSrc[j] = (half ? g_Wbl : g_Wbh) + (size_t)n * KEPI + c * 8;
        bDst[j] = smem_u32(sm) + (half ? EBL_OFF : EBH_OFF) + n * BPITCH + c * 16;
    }

    const int aRow = m0w + (lane & 7) + ((lane >> 3) & 1) * 8;
    const int aCol = ((lane >> 4) & 1) * 16;
    const uint32_t aBaseH = smem_u32(sm) + EAH_OFF + aRow * APITCH + aCol;
    const uint32_t aBaseL = smem_u32(sm) + EAL_OFF + aRow * APITCH + aCol;
    const int bRow = n0w + ((lane >> 4) & 1) * 8 + (lane & 7);
    const int bCol = ((lane >> 3) & 1) * 16;
    const uint32_t bBaseH = smem_u32(sm) + EBH_OFF + bRow * BPITCH + bCol;
    const uint32_t bBaseL = smem_u32(sm) + EBL_OFF + bRow * BPITCH + bCol;

    float acc[8][4];
    #pragma unroll
    for (int nf = 0; nf < 8; nf++)
        #pragma unroll
        for (int q = 0; q < 4; q++) acc[nf][q] = 0.0f;

    {
        float4 av = loadT(X, aRowG, acl * 4);
        #pragma unroll
        for (int j = 0; j < 8; j++) cp16(bDst[j], bSrc[j]);
        cp_commit();
        split_sts(aHiDst, aLoDst, av);
        cp_wait0();
        __syncthreads();
    }

    for (int t = 0; t < NCHUNK_E; t++) {
        const int cur = t & 1, nxt = cur ^ 1;
        const bool more = (t + 1 < NCHUNK_E);
        float4 av;
        if (more) {
            av = loadT(X, aRowG, (t + 1) * KC + acl * 4);
            #pragma unroll
            for (int j = 0; j < 8; j++)
                cp16(bDst[j] + nxt * ESTG, bSrc[j] + (size_t)(t + 1) * KC);
            cp_commit();
        }

        const uint32_t soff = cur * ESTG;
        #pragma unroll
        for (int j16 = 0; j16 < 2; j16++) {
            const int kb = j16 * 32;
            uint32_t ah[4], al[4];
            ldsm4(ah, aBaseH + soff + kb);
            ldsm4(al, aBaseL + soff + kb);
            #pragma unroll
            for (int np = 0; np < 4; np++) {
                uint32_t bh[4], bl[4];
                ldsm4(bh, bBaseH + soff + np * 16 * BPITCH + kb);
                ldsm4(bl, bBaseL + soff + np * 16 * BPITCH + kb);
                #pragma unroll
                for (int h = 0; h < 2; h++) {
                    const int nf = 2 * np + h;
                    uint32_t b0h = bh[2 * h], b1h = bh[2 * h + 1];
                    uint32_t b0l = bl[2 * h], b1l = bl[2 * h + 1];
                    mma16816(acc[nf], ah, b0h, b1h);
                    mma16816(acc[nf], al, b0h, b1h);
                    mma16816(acc[nf], ah, b0l, b1l);
                }
            }
        }

        if (more)
            split_sts(aHiDst + nxt * ESTG, aLoDst + nxt * ESTG, av);
        cp_wait0();
        __syncthreads();
    }

    float* Cp = C + (size_t)(bx * 32) * DDIM;
    #pragma unroll
    for (int nf = 0; nf < 8; nf++) {
        int r = m0w + g;
        int c = n0w + nf * 8 + 2 * t4;
        float2 bias = *reinterpret_cast<const float2*>(g_bias + c);
        float2 v0 = make_float2(fmaxf(acc[nf][0] + bias.x, 0.0f),
                                fmaxf(acc[nf][1] + bias.y, 0.0f));
        float2 v1 = make_float2(fmaxf(acc[nf][2] + bias.x, 0.0f),
                                fmaxf(acc[nf][3] + bias.y, 0.0f));
        *reinterpret_cast<float2*>(Cp + (size_t)r * DDIM + c)       = v0;
        *reinterpret_cast<float2*>(Cp + (size_t)(r + 8) * DDIM + c) = v1;
    }
}

// =============== launch ===============
extern "C" void kernel_launch(void* const* d_in, const int* in_sizes, int n_in,
                              void* d_out, int out_size) {
    const float *X = nullptr, *A = nullptr, *W = nullptr, *b = nullptr;
    for (int i = 0; i < n_in; i++) {
        long long s = in_sizes[i];
        if      (s == (long long)PP * NROWS * NROWS) A = (const float*)d_in[i];
        else if (s == (long long)NROWS * DDIM)       X = (const float*)d_in[i];
        else if (s == (long long)PP * DDIM * DDIM)   W = (const float*)d_in[i];
        else if (s == (long long)PP * DDIM)          b = (const float*)d_in[i];
    }
    cudaFuncSetAttribute(gemm1_kernel,
                         cudaFuncAttributeMaxDynamicSharedMemorySize, G1_SMEM);
    cudaFuncSetAttribute(gemm_epi_kernel,
                         cudaFuncAttributeMaxDynamicSharedMemorySize, EPI_SMEM);

    prep_kernel<<<(3 * DDIM * DDIM + 255) / 256, 256>>>(W, b);
    xt_kernel<<<dim3(NROWS / 32, DDIM / 32), dim3(32, 8)>>>(X);
    gemm1_kernel<<<dim3(NROWS / 64, PP), 256, G1_SMEM>>>(A);
    gemm_epi_kernel<<<NROWS / 32, 256, EPI_SMEM>>>(X, (float*)d_out);
}

// round 15
// speedup vs baseline: 1.8112x; 1.4658x over previous
#include <cuda_runtime.h>
#include <cuda_bf16.h>
#include <cuda_fp16.h>
#include <cstdint>

#define NROWS 8192
#define DDIM  256
#define PP    3
#define KC    32
#define NCHUNK (NROWS / KC)      // 256
#define KEPI   (3 * DDIM)        // 768
#define NCHUNK_E (KEPI / KC)     // 24

// gemm1 smem layout (per stage), 80B-padded rows: A hi/lo fp16 + B single fp16
#define APITCH 80
#define BPITCH 80
#define AH_OFF 0
#define AL_OFF 5120
#define BF_OFF 10240
#define STG    30720
#define G1_SMEM (2 * STG)        // 61440

// epi smem layout (M=32 tiles, bf16 3-term — unchanged from R13)
#define EAH_OFF 0
#define EAL_OFF 2560
#define EBH_OFF 5120
#define EBL_OFF 25600
#define ESTG    46080
#define EPI_SMEM (2 * ESTG)      // 92160

// ---- scratch (device globals; no allocation allowed) ----
__device__ __align__(16) float g_M[PP * NROWS * DDIM];
__device__ __align__(16) float g_bias[DDIM];
__device__ __align__(16) __half g_Xtf[DDIM * NROWS];          // X^T fp16 [d][k]
__device__ __align__(16) __nv_bfloat16 g_Wbh[DDIM * KEPI];    // W as B[n][k] hi
__device__ __align__(16) __nv_bfloat16 g_Wbl[DDIM * KEPI];    // W as B[n][k] lo

// =============== helpers ===============
__device__ __forceinline__ unsigned smem_u32(const void* p) {
    return (unsigned)__cvta_generic_to_shared(p);
}
__device__ __forceinline__ void cp16(unsigned dst, const void* src) {
    asm volatile("cp.async.cg.shared.global [%0], [%1], 16;" :: "r"(dst), "l"(src));
}
__device__ __forceinline__ void cp_commit() { asm volatile("cp.async.commit_group;"); }
__device__ __forceinline__ void cp_wait0()  { asm volatile("cp.async.wait_group 0;"); }

__device__ __forceinline__ void sts64(uint32_t addr, uint32_t v0, uint32_t v1) {
    asm volatile("st.shared.v2.b32 [%0], {%1, %2};" :: "r"(addr), "r"(v0), "r"(v1) : "memory");
}

// ldmatrix x4 (sm_75+, legal at plain sm_103)
__device__ __forceinline__ void ldsm4(uint32_t* r, uint32_t addr) {
    asm volatile("ldmatrix.sync.aligned.m8n8.x4.shared.b16 {%0,%1,%2,%3}, [%4];"
                 : "=r"(r[0]), "=r"(r[1]), "=r"(r[2]), "=r"(r[3]) : "r"(addr));
}

// HMMA m16n8k16 bf16 (epi)
__device__ __forceinline__ void mma16816(float* c, const uint32_t* a,
                                         uint32_t b0, uint32_t b1) {
    asm("mma.sync.aligned.m16n8k16.row.col.f32.bf16.bf16.f32 "
        "{%0,%1,%2,%3}, {%4,%5,%6,%7}, {%8,%9}, {%0,%1,%2,%3};"
        : "+f"(c[0]), "+f"(c[1]), "+f"(c[2]), "+f"(c[3])
        : "r"(a[0]), "r"(a[1]), "r"(a[2]), "r"(a[3]), "r"(b0), "r"(b1));
}
// HMMA m16n8k16 fp16 (gemm1)
__device__ __forceinline__ void mma16816h(float* c, const uint32_t* a,
                                          uint32_t b0, uint32_t b1) {
    asm("mma.sync.aligned.m16n8k16.row.col.f32.f16.f16.f32 "
        "{%0,%1,%2,%3}, {%4,%5,%6,%7}, {%8,%9}, {%0,%1,%2,%3};"
        : "+f"(c[0]), "+f"(c[1]), "+f"(c[2]), "+f"(c[3])
        : "r"(a[0]), "r"(a[1]), "r"(a[2]), "r"(a[3]), "r"(b0), "r"(b1));
}

// bf16 hi/lo split store (epi producer)
__device__ __forceinline__ void split_sts(uint32_t hiAddr, uint32_t loAddr, float4 v) {
    __nv_bfloat162 h01 = __floats2bfloat162_rn(v.x, v.y);
    __nv_bfloat162 h23 = __floats2bfloat162_rn(v.z, v.w);
    float2 f01 = __bfloat1622float2(h01);
    float2 f23 = __bfloat1622float2(h23);
    __nv_bfloat162 l01 = __floats2bfloat162_rn(v.x - f01.x, v.y - f01.y);
    __nv_bfloat162 l23 = __floats2bfloat162_rn(v.z - f23.x, v.w - f23.y);
    sts64(hiAddr, *reinterpret_cast<uint32_t*>(&h01), *reinterpret_cast<uint32_t*>(&h23));
    sts64(loAddr, *reinterpret_cast<uint32_t*>(&l01), *reinterpret_cast<uint32_t*>(&l23));
}
// fp16 hi/lo split store (gemm1 producer)
__device__ __forceinline__ void split_sts_h(uint32_t hiAddr, uint32_t loAddr, float4 v) {
    __half2 h01 = __floats2half2_rn(v.x, v.y);
    __half2 h23 = __floats2half2_rn(v.z, v.w);
    float2 f01 = __half22float2(h01);
    float2 f23 = __half22float2(h23);
    __half2 l01 = __floats2half2_rn(v.x - f01.x, v.y - f01.y);
    __half2 l23 = __floats2half2_rn(v.z - f23.x, v.w - f23.y);
    sts64(hiAddr, *reinterpret_cast<uint32_t*>(&h01), *reinterpret_cast<uint32_t*>(&h23));
    sts64(loAddr, *reinterpret_cast<uint32_t*>(&l01), *reinterpret_cast<uint32_t*>(&l23));
}

// =============== X^T transpose + fp16 convert ===============
__global__ void xt_kernel(const float* __restrict__ X) {
    __shared__ float tile[32][33];
    int k0 = blockIdx.x * 32, d0 = blockIdx.y * 32;
    int tx = threadIdx.x, ty = threadIdx.y;     // 32 x 8
    #pragma unroll
    for (int i = 0; i < 4; i++)
        tile[ty + 8 * i][tx] = X[(size_t)(k0 + ty + 8 * i) * DDIM + d0 + tx];
    __syncthreads();
    #pragma unroll
    for (int i = 0; i < 4; i++) {
        int d = d0 + ty + 8 * i, k = k0 + tx;
        g_Xtf[(size_t)d * NROWS + k] = __float2half_rn(tile[tx][ty + 8 * i]);
    }
}

// =============== prep: W -> B[n][k] bf16 hi/lo + fused bias ===============
__global__ void prep_kernel(const float* __restrict__ W, const float* __restrict__ b) {
    int idx = blockIdx.x * blockDim.x + threadIdx.x;
    if (idx < 3 * DDIM * DDIM) {
        int kk = idx & (DDIM - 1);
        int rd = idx >> 8;
        int d  = rd & (DDIM - 1);
        int r  = rd >> 8;
        float v = W[idx];
        __nv_bfloat16 h = __float2bfloat16(v);
        __nv_bfloat16 l = __float2bfloat16(v - __bfloat162float(h));
        int k = r * DDIM + kk;
        g_Wbh[d * KEPI + k] = h;
        g_Wbl[d * KEPI + k] = l;
    }
    if (idx < DDIM)
        g_bias[idx] = b[idx] + 3.0f * b[DDIM + idx] + 6.0f * b[2 * DDIM + idx];
}

// ===== gemm1: M_p = A_p @ X  (HMMA fp16, A 2-term split, X single fp16) ========
// CTA: 64 x 256, BK=32, 256 threads, 8 warps (2 m-groups x 4 n-groups),
// warp tile 32 x 64. 2 MMAs per (mf,nf) per k16-step.
__global__ __launch_bounds__(256, 2)
void gemm1_kernel(const float* __restrict__ A) {
    extern __shared__ char sm[];

    const int tid  = threadIdx.x;
    const int wid  = tid >> 5;
    const int lane = tid & 31;
    const int g    = lane >> 2;
    const int t4   = lane & 3;
    const int m0w  = (wid >> 2) * 32;
    const int n0w  = (wid & 3) * 64;
    const int bx = blockIdx.x, p = blockIdx.y;

    const float* Ap = A + (size_t)p * NROWS * NROWS + (size_t)bx * 64 * NROWS;

    const float* aSrc[2];
    uint32_t aHiDst[2], aLoDst[2];
    #pragma unroll
    for (int j = 0; j < 2; j++) {
        int idx = j * 256 + tid;
        int r = idx >> 3, c = idx & 7;
        aSrc[j]  = Ap + (size_t)r * NROWS + c * 4;
        aHiDst[j] = smem_u32(sm) + AH_OFF + r * APITCH + c * 8;
        aLoDst[j] = smem_u32(sm) + AL_OFF + r * APITCH + c * 8;
    }
    // B: 256 rows x 64B data -> 1024 cp16 per chunk -> 4 per thread
    const __half* bSrc[4];
    uint32_t bDst[4];
    #pragma unroll
    for (int j = 0; j < 4; j++) {
        int idx = j * 256 + tid;            // 0..1023
        int n = idx >> 2, c = idx & 3;
        bSrc[j] = g_Xtf + (size_t)n * NROWS + c * 8;
        bDst[j] = smem_u32(sm) + BF_OFF + n * BPITCH + c * 16;
    }

    const int aRow = m0w + (lane & 7) + ((lane >> 3) & 1) * 8;
    const int aCol = ((lane >> 4) & 1) * 16;
    const uint32_t aBaseH = smem_u32(sm) + AH_OFF + aRow * APITCH + aCol;
    const uint32_t aBaseL = smem_u32(sm) + AL_OFF + aRow * APITCH + aCol;
    const int bRow = n0w + ((lane >> 4) & 1) * 8 + (lane & 7);
    const int bCol = ((lane >> 3) & 1) * 16;
    const uint32_t bBase = smem_u32(sm) + BF_OFF + bRow * BPITCH + bCol;

    float acc[2][8][4];
    #pragma unroll
    for (int mf = 0; mf < 2; mf++)
        #pragma unroll
        for (int nf = 0; nf < 8; nf++)
            #pragma unroll
            for (int q = 0; q < 4; q++) acc[mf][nf][q] = 0.0f;

    {
        float4 av[2];
        #pragma unroll
        for (int j = 0; j < 2; j++) av[j] = *reinterpret_cast<const float4*>(aSrc[j]);
        #pragma unroll
        for (int j = 0; j < 4; j++) cp16(bDst[j], bSrc[j]);
        cp_commit();
        #pragma unroll
        for (int j = 0; j < 2; j++) split_sts_h(aHiDst[j], aLoDst[j], av[j]);
        cp_wait0();
        __syncthreads();
    }

    for (int t = 0; t < NCHUNK; t++) {
        const int cur = t & 1, nxt = cur ^ 1;
        const bool more = (t + 1 < NCHUNK);
        float4 av[2];
        if (more) {
            #pragma unroll
            for (int j = 0; j < 2; j++)
                av[j] = *reinterpret_cast<const float4*>(aSrc[j] + (size_t)(t + 1) * KC);
            #pragma unroll
            for (int j = 0; j < 4; j++)
                cp16(bDst[j] + nxt * STG, bSrc[j] + (size_t)(t + 1) * KC);
            cp_commit();
        }

        const uint32_t soff = cur * STG;
        #pragma unroll
        for (int j16 = 0; j16 < 2; j16++) {
            const int kb = j16 * 32;
            uint32_t ah[2][4], al[2][4];
            ldsm4(ah[0], aBaseH + soff + kb);
            ldsm4(ah[1], aBaseH + soff + 16 * APITCH + kb);
            ldsm4(al[0], aBaseL + soff + kb);
            ldsm4(al[1], aBaseL + soff + 16 * APITCH + kb);
            #pragma unroll
            for (int np = 0; np < 4; np++) {
                uint32_t bq[4];
                ldsm4(bq, bBase + soff + np * 16 * BPITCH + kb);
                #pragma unroll
                for (int h = 0; h < 2; h++) {
                    const int nf = 2 * np + h;
                    uint32_t b0 = bq[2 * h], b1 = bq[2 * h + 1];
                    #pragma unroll
                    for (int mf = 0; mf < 2; mf++) {
                        mma16816h(acc[mf][nf], ah[mf], b0, b1);
                        mma16816h(acc[mf][nf], al[mf], b0, b1);
                    }
                }
            }
        }

        if (more) {
            #pragma unroll
            for (int j = 0; j < 2; j++)
                split_sts_h(aHiDst[j] + nxt * STG, aLoDst[j] + nxt * STG, av[j]);
        }
        cp_wait0();
        __syncthreads();
    }

    float* Mout = g_M + (size_t)p * NROWS * DDIM + (size_t)bx * 64 * DDIM;
    #pragma unroll
    for (int mf = 0; mf < 2; mf++) {
        #pragma unroll
        for (int nf = 0; nf < 8; nf++) {
            int r = m0w + mf * 16 + g;
            int c = n0w + nf * 8 + 2 * t4;
            *reinterpret_cast<float2*>(Mout + (size_t)r * DDIM + c) =
                make_float2(acc[mf][nf][0], acc[mf][nf][1]);
            *reinterpret_cast<float2*>(Mout + (size_t)(r + 8) * DDIM + c) =
                make_float2(acc[mf][nf][2], acc[mf][nf][3]);
        }
    }
}

// ===== T row compute on the fly: region = k>>8, uniform per chunk =====
__device__ __forceinline__ float4 loadT(const float* __restrict__ X, int row, int k) {
    const int kk = k & 255;
    const size_t off = (size_t)row * DDIM + kk;
    const int region = k >> 8;
    if (region == 0) return *reinterpret_cast<const float4*>(X + off);
    float4 m0 = *reinterpret_cast<const float4*>(g_M + off);
    float4 m1 = *reinterpret_cast<const float4*>(g_M + (size_t)NROWS * DDIM + off);
    float4 m2 = *reinterpret_cast<const float4*>(g_M + 2 * (size_t)NROWS * DDIM + off);
    float4 s1;
    s1.x = m0.x + m1.x + m2.x;  s1.y = m0.y + m1.y + m2.y;
    s1.z = m0.z + m1.z + m2.z;  s1.w = m0.w + m1.w + m2.w;
    if (region == 1) return s1;
    float4 s2;
    s2.x = 0.5f * (s1.x * s1.x + m0.x * m0.x + m1.x * m1.x + m2.x * m2.x);
    s2.y = 0.5f * (s1.y * s1.y + m0.y * m0.y + m1.y * m1.y + m2.y * m2.y);
    s2.z = 0.5f * (s1.z * s1.z + m0.z * m0.z + m1.z * m1.z + m2.z * m2.z);
    s2.w = 0.5f * (s1.w * s1.w + m0.w * m0.w + m1.w * m1.w + m2.w * m2.w);
    return s2;
}

// ===== epilogue GEMM (HMMA bf16 3-term): out = relu(T @ W^T + bias), M=32 =====
__global__ __launch_bounds__(256, 2)
void gemm_epi_kernel(const float* __restrict__ X, float* __restrict__ C) {
    extern __shared__ char sm[];

    const int tid  = threadIdx.x;
    const int wid  = tid >> 5;
    const int lane = tid & 31;
    const int g    = lane >> 2;
    const int t4   = lane & 3;
    const int m0w  = (wid >> 2) * 16;
    const int n0w  = (wid & 3) * 64;
    const int bx = blockIdx.x;

    const int arw = tid >> 3, acl = tid & 7;
    const int aRowG = bx * 32 + arw;
    const uint32_t aHiDst = smem_u32(sm) + EAH_OFF + arw * APITCH + acl * 8;
    const uint32_t aLoDst = smem_u32(sm) + EAL_OFF + arw * APITCH + acl * 8;
    const __nv_bfloat16* bSrc[8];
    uint32_t bDst[8];
    #pragma unroll
    for (int j = 0; j < 8; j++) {
        int idx = j * 256 + tid;
        int half_ = idx >> 10;
        int q = idx & 1023;
        int n = q >> 2, c = q & 3;
        bSrc[j] = (half_ ? g_Wbl : g_Wbh) + (size_t)n * KEPI + c * 8;
        bDst[j] = smem_u32(sm) + (half_ ? EBL_OFF : EBH_OFF) + n * BPITCH + c * 16;
    }

    const int aRow = m0w + (lane & 7) + ((lane >> 3) & 1) * 8;
    const int aCol = ((lane >> 4) & 1) * 16;
    const uint32_t aBaseH = smem_u32(sm) + EAH_OFF + aRow * APITCH + aCol;
    const uint32_t aBaseL = smem_u32(sm) + EAL_OFF + aRow * APITCH + aCol;
    const int bRow = n0w + ((lane >> 4) & 1) * 8 + (lane & 7);
    const int bCol = ((lane >> 3) & 1) * 16;
    const uint32_t bBaseH = smem_u32(sm) + EBH_OFF + bRow * BPITCH + bCol;
    const uint32_t bBaseL = smem_u32(sm) + EBL_OFF + bRow * BPITCH + bCol;

    float acc[8][4];
    #pragma unroll
    for (int nf = 0; nf < 8; nf++)
        #pragma unroll
        for (int q = 0; q < 4; q++) acc[nf][q] = 0.0f;

    {
        float4 av = loadT(X, aRowG, acl * 4);
        #pragma unroll
        for (int j = 0; j < 8; j++) cp16(bDst[j], bSrc[j]);
        cp_commit();
        split_sts(aHiDst, aLoDst, av);
        cp_wait0();
        __syncthreads();
    }

    for (int t = 0; t < NCHUNK_E; t++) {
        const int cur = t & 1, nxt = cur ^ 1;
        const bool more = (t + 1 < NCHUNK_E);
        float4 av;
        if (more) {
            av = loadT(X, aRowG, (t + 1) * KC + acl * 4);
            #pragma unroll
            for (int j = 0; j < 8; j++)
                cp16(bDst[j] + nxt * ESTG, bSrc[j] + (size_t)(t + 1) * KC);
            cp_commit();
        }

        const uint32_t soff = cur * ESTG;
        #pragma unroll
        for (int j16 = 0; j16 < 2; j16++) {
            const int kb = j16 * 32;
            uint32_t ah[4], al[4];
            ldsm4(ah, aBaseH + soff + kb);
            ldsm4(al, aBaseL + soff + kb);
            #pragma unroll
            for (int np = 0; np < 4; np++) {
                uint32_t bh[4], bl[4];
                ldsm4(bh, bBaseH + soff + np * 16 * BPITCH + kb);
                ldsm4(bl, bBaseL + soff + np * 16 * BPITCH + kb);
                #pragma unroll
                for (int h = 0; h < 2; h++) {
                    const int nf = 2 * np + h;
                    uint32_t b0h = bh[2 * h], b1h = bh[2 * h + 1];
                    uint32_t b0l = bl[2 * h], b1l = bl[2 * h + 1];
                    mma16816(acc[nf], ah, b0h, b1h);
                    mma16816(acc[nf], al, b0h, b1h);
                    mma16816(acc[nf], ah, b0l, b1l);
                }
            }
        }

        if (more)
            split_sts(aHiDst + nxt * ESTG, aLoDst + nxt * ESTG, av);
        cp_wait0();
        __syncthreads();
    }

    float* Cp = C + (size_t)(bx * 32) * DDIM;
    #pragma unroll
    for (int nf = 0; nf < 8; nf++) {
        int r = m0w + g;
        int c = n0w + nf * 8 + 2 * t4;
        float2 bias = *reinterpret_cast<const float2*>(g_bias + c);
        float2 v0 = make_float2(fmaxf(acc[nf][0] + bias.x, 0.0f),
                                fmaxf(acc[nf][1] + bias.y, 0.0f));
        float2 v1 = make_float2(fmaxf(acc[nf][2] + bias.x, 0.0f),
                                fmaxf(acc[nf][3] + bias.y, 0.0f));
        *reinterpret_cast<float2*>(Cp + (size_t)r * DDIM + c)       = v0;
        *reinterpret_cast<float2*>(Cp + (size_t)(r + 8) * DDIM + c) = v1;
    }
}

// =============== launch ===============
extern "C" void kernel_launch(void* const* d_in, const int* in_sizes, int n_in,
                              void* d_out, int out_size) {
    const float *X = nullptr, *A = nullptr, *W = nullptr, *b = nullptr;
    for (int i = 0; i < n_in; i++) {
        long long s = in_sizes[i];
        if      (s == (long long)PP * NROWS * NROWS) A = (const float*)d_in[i];
        else if (s == (long long)NROWS * DDIM)       X = (const float*)d_in[i];
        else if (s == (long long)PP * DDIM * DDIM)   W = (const float*)d_in[i];
        else if (s == (long long)PP * DDIM)          b = (const float*)d_in[i];
    }
    cudaFuncSetAttribute(gemm1_kernel,
                         cudaFuncAttributeMaxDynamicSharedMemorySize, G1_SMEM);
    cudaFuncSetAttribute(gemm_epi_kernel,
                         cudaFuncAttributeMaxDynamicSharedMemorySize, EPI_SMEM);

    prep_kernel<<<(3 * DDIM * DDIM + 255) / 256, 256>>>(W, b);
    xt_kernel<<<dim3(NROWS / 32, DDIM / 32), dim3(32, 8)>>>(X);
    gemm1_kernel<<<dim3(NROWS / 64, PP), 256, G1_SMEM>>>(A);
    gemm_epi_kernel<<<NROWS / 32, 256, EPI_SMEM>>>(X, (float*)d_out);
}

// round 16
// speedup vs baseline: 2.1946x; 1.2117x over previous
#include <cuda_runtime.h>
#include <cuda_bf16.h>
#include <cuda_fp16.h>
#include <cstdint>

#define NROWS 8192
#define DDIM  256
#define PP    3
#define KC    32
#define NCHUNK (NROWS / KC)      // 256
#define KEPI   (3 * DDIM)        // 768
#define NCHUNK_E (KEPI / KC)     // 24

// gemm1 smem layout (per stage), 80B-padded rows: A single fp16 + B single fp16
#define APITCH 80
#define BPITCH 80
#define AH_OFF 0
#define BF_OFF 5120
#define STG    25600
#define G1_SMEM (2 * STG)        // 51200

// epi smem layout (M=32 tiles, bf16 3-term — unchanged from R13)
#define EAH_OFF 0
#define EAL_OFF 2560
#define EBH_OFF 5120
#define EBL_OFF 25600
#define ESTG    46080
#define EPI_SMEM (2 * ESTG)      // 92160

// ---- scratch (device globals; no allocation allowed) ----
__device__ __align__(16) float g_M[PP * NROWS * DDIM];
__device__ __align__(16) float g_bias[DDIM];
__device__ __align__(16) __half g_Xtf[DDIM * NROWS];          // X^T fp16 [d][k]
__device__ __align__(16) __nv_bfloat16 g_Wbh[DDIM * KEPI];    // W as B[n][k] hi
__device__ __align__(16) __nv_bfloat16 g_Wbl[DDIM * KEPI];    // W as B[n][k] lo

// =============== helpers ===============
__device__ __forceinline__ unsigned smem_u32(const void* p) {
    return (unsigned)__cvta_generic_to_shared(p);
}
__device__ __forceinline__ void cp16(unsigned dst, const void* src) {
    asm volatile("cp.async.cg.shared.global [%0], [%1], 16;" :: "r"(dst), "l"(src));
}
__device__ __forceinline__ void cp_commit() { asm volatile("cp.async.commit_group;"); }
__device__ __forceinline__ void cp_wait0()  { asm volatile("cp.async.wait_group 0;"); }

__device__ __forceinline__ void sts64(uint32_t addr, uint32_t v0, uint32_t v1) {
    asm volatile("st.shared.v2.b32 [%0], {%1, %2};" :: "r"(addr), "r"(v0), "r"(v1) : "memory");
}

// ldmatrix x4 (sm_75+, legal at plain sm_103)
__device__ __forceinline__ void ldsm4(uint32_t* r, uint32_t addr) {
    asm volatile("ldmatrix.sync.aligned.m8n8.x4.shared.b16 {%0,%1,%2,%3}, [%4];"
                 : "=r"(r[0]), "=r"(r[1]), "=r"(r[2]), "=r"(r[3]) : "r"(addr));
}

// HMMA m16n8k16 bf16 (epi)
__device__ __forceinline__ void mma16816(float* c, const uint32_t* a,
                                         uint32_t b0, uint32_t b1) {
    asm("mma.sync.aligned.m16n8k16.row.col.f32.bf16.bf16.f32 "
        "{%0,%1,%2,%3}, {%4,%5,%6,%7}, {%8,%9}, {%0,%1,%2,%3};"
        : "+f"(c[0]), "+f"(c[1]), "+f"(c[2]), "+f"(c[3])
        : "r"(a[0]), "r"(a[1]), "r"(a[2]), "r"(a[3]), "r"(b0), "r"(b1));
}
// HMMA m16n8k16 fp16 (gemm1)
__device__ __forceinline__ void mma16816h(float* c, const uint32_t* a,
                                          uint32_t b0, uint32_t b1) {
    asm("mma.sync.aligned.m16n8k16.row.col.f32.f16.f16.f32 "
        "{%0,%1,%2,%3}, {%4,%5,%6,%7}, {%8,%9}, {%0,%1,%2,%3};"
        : "+f"(c[0]), "+f"(c[1]), "+f"(c[2]), "+f"(c[3])
        : "r"(a[0]), "r"(a[1]), "r"(a[2]), "r"(a[3]), "r"(b0), "r"(b1));
}

// bf16 hi/lo split store (epi producer)
__device__ __forceinline__ void split_sts(uint32_t hiAddr, uint32_t loAddr, float4 v) {
    __nv_bfloat162 h01 = __floats2bfloat162_rn(v.x, v.y);
    __nv_bfloat162 h23 = __floats2bfloat162_rn(v.z, v.w);
    float2 f01 = __bfloat1622float2(h01);
    float2 f23 = __bfloat1622float2(h23);
    __nv_bfloat162 l01 = __floats2bfloat162_rn(v.x - f01.x, v.y - f01.y);
    __nv_bfloat162 l23 = __floats2bfloat162_rn(v.z - f23.x, v.w - f23.y);
    sts64(hiAddr, *reinterpret_cast<uint32_t*>(&h01), *reinterpret_cast<uint32_t*>(&h23));
    sts64(loAddr, *reinterpret_cast<uint32_t*>(&l01), *reinterpret_cast<uint32_t*>(&l23));
}
// plain fp16 convert store (gemm1 producer)
__device__ __forceinline__ void cvt_sts_h(uint32_t addr, float4 v) {
    __half2 h01 = __floats2half2_rn(v.x, v.y);
    __half2 h23 = __floats2half2_rn(v.z, v.w);
    sts64(addr, *reinterpret_cast<uint32_t*>(&h01), *reinterpret_cast<uint32_t*>(&h23));
}

// =============== X^T transpose + fp16 convert ===============
__global__ void xt_kernel(const float* __restrict__ X) {
    __shared__ float tile[32][33];
    int k0 = blockIdx.x * 32, d0 = blockIdx.y * 32;
    int tx = threadIdx.x, ty = threadIdx.y;     // 32 x 8
    #pragma unroll
    for (int i = 0; i < 4; i++)
        tile[ty + 8 * i][tx] = X[(size_t)(k0 + ty + 8 * i) * DDIM + d0 + tx];
    __syncthreads();
    #pragma unroll
    for (int i = 0; i < 4; i++) {
        int d = d0 + ty + 8 * i, k = k0 + tx;
        g_Xtf[(size_t)d * NROWS + k] = __float2half_rn(tile[tx][ty + 8 * i]);
    }
}

// =============== prep: W -> B[n][k] bf16 hi/lo + fused bias ===============
__global__ void prep_kernel(const float* __restrict__ W, const float* __restrict__ b) {
    int idx = blockIdx.x * blockDim.x + threadIdx.x;
    if (idx < 3 * DDIM * DDIM) {
        int kk = idx & (DDIM - 1);
        int rd = idx >> 8;
        int d  = rd & (DDIM - 1);
        int r  = rd >> 8;
        float v = W[idx];
        __nv_bfloat16 h = __float2bfloat16(v);
        __nv_bfloat16 l = __float2bfloat16(v - __bfloat162float(h));
        int k = r * DDIM + kk;
        g_Wbh[d * KEPI + k] = h;
        g_Wbl[d * KEPI + k] = l;
    }
    if (idx < DDIM)
        g_bias[idx] = b[idx] + 3.0f * b[DDIM + idx] + 6.0f * b[2 * DDIM + idx];
}

// ===== gemm1: M_p = A_p @ X  (HMMA fp16, single-term A and X) ==================
// CTA: 64 x 256, BK=32, 256 threads, 8 warps (2 m-groups x 4 n-groups),
// warp tile 32 x 64. 1 MMA per (mf,nf) per k16-step.
__global__ __launch_bounds__(256, 2)
void gemm1_kernel(const float* __restrict__ A) {
    extern __shared__ char sm[];

    const int tid  = threadIdx.x;
    const int wid  = tid >> 5;
    const int lane = tid & 31;
    const int g    = lane >> 2;
    const int t4   = lane & 3;
    const int m0w  = (wid >> 2) * 32;
    const int n0w  = (wid & 3) * 64;
    const int bx = blockIdx.x, p = blockIdx.y;

    const float* Ap = A + (size_t)p * NROWS * NROWS + (size_t)bx * 64 * NROWS;

    const float* aSrc[2];
    uint32_t aDst[2];
    #pragma unroll
    for (int j = 0; j < 2; j++) {
        int idx = j * 256 + tid;
        int r = idx >> 3, c = idx & 7;
        aSrc[j] = Ap + (size_t)r * NROWS + c * 4;
        aDst[j] = smem_u32(sm) + AH_OFF + r * APITCH + c * 8;
    }
    // B: 256 rows x 64B data -> 1024 cp16 per chunk -> 4 per thread
    const __half* bSrc[4];
    uint32_t bDst[4];
    #pragma unroll
    for (int j = 0; j < 4; j++) {
        int idx = j * 256 + tid;            // 0..1023
        int n = idx >> 2, c = idx & 3;
        bSrc[j] = g_Xtf + (size_t)n * NROWS + c * 8;
        bDst[j] = smem_u32(sm) + BF_OFF + n * BPITCH + c * 16;
    }

    const int aRow = m0w + (lane & 7) + ((lane >> 3) & 1) * 8;
    const int aCol = ((lane >> 4) & 1) * 16;
    const uint32_t aBase = smem_u32(sm) + AH_OFF + aRow * APITCH + aCol;
    const int bRow = n0w + ((lane >> 4) & 1) * 8 + (lane & 7);
    const int bCol = ((lane >> 3) & 1) * 16;
    const uint32_t bBase = smem_u32(sm) + BF_OFF + bRow * BPITCH + bCol;

    float acc[2][8][4];
    #pragma unroll
    for (int mf = 0; mf < 2; mf++)
        #pragma unroll
        for (int nf = 0; nf < 8; nf++)
            #pragma unroll
            for (int q = 0; q < 4; q++) acc[mf][nf][q] = 0.0f;

    {
        float4 av[2];
        #pragma unroll
        for (int j = 0; j < 2; j++) av[j] = *reinterpret_cast<const float4*>(aSrc[j]);
        #pragma unroll
        for (int j = 0; j < 4; j++) cp16(bDst[j], bSrc[j]);
        cp_commit();
        #pragma unroll
        for (int j = 0; j < 2; j++) cvt_sts_h(aDst[j], av[j]);
        cp_wait0();
        __syncthreads();
    }

    for (int t = 0; t < NCHUNK; t++) {
        const int cur = t & 1, nxt = cur ^ 1;
        const bool more = (t + 1 < NCHUNK);
        float4 av[2];
        if (more) {
            #pragma unroll
            for (int j = 0; j < 2; j++)
                av[j] = *reinterpret_cast<const float4*>(aSrc[j] + (size_t)(t + 1) * KC);
            #pragma unroll
            for (int j = 0; j < 4; j++)
                cp16(bDst[j] + nxt * STG, bSrc[j] + (size_t)(t + 1) * KC);
            cp_commit();
        }

        const uint32_t soff = cur * STG;
        #pragma unroll
        for (int j16 = 0; j16 < 2; j16++) {
            const int kb = j16 * 32;
            uint32_t ah[2][4];
            ldsm4(ah[0], aBase + soff + kb);
            ldsm4(ah[1], aBase + soff + 16 * APITCH + kb);
            #pragma unroll
            for (int np = 0; np < 4; np++) {
                uint32_t bq[4];
                ldsm4(bq, bBase + soff + np * 16 * BPITCH + kb);
                #pragma unroll
                for (int h = 0; h < 2; h++) {
                    const int nf = 2 * np + h;
                    uint32_t b0 = bq[2 * h], b1 = bq[2 * h + 1];
                    #pragma unroll
                    for (int mf = 0; mf < 2; mf++)
                        mma16816h(acc[mf][nf], ah[mf], b0, b1);
                }
            }
        }

        if (more) {
            #pragma unroll
            for (int j = 0; j < 2; j++)
                cvt_sts_h(aDst[j] + nxt * STG, av[j]);
        }
        cp_wait0();
        __syncthreads();
    }

    float* Mout = g_M + (size_t)p * NROWS * DDIM + (size_t)bx * 64 * DDIM;
    #pragma unroll
    for (int mf = 0; mf < 2; mf++) {
        #pragma unroll
        for (int nf = 0; nf < 8; nf++) {
            int r = m0w + mf * 16 + g;
            int c = n0w + nf * 8 + 2 * t4;
            *reinterpret_cast<float2*>(Mout + (size_t)r * DDIM + c) =
                make_float2(acc[mf][nf][0], acc[mf][nf][1]);
            *reinterpret_cast<float2*>(Mout + (size_t)(r + 8) * DDIM + c) =
                make_float2(acc[mf][nf][2], acc[mf][nf][3]);
        }
    }
}

// ===== T row compute on the fly: region = k>>8, uniform per chunk =====
__device__ __forceinline__ float4 loadT(const float* __restrict__ X, int row, int k) {
    const int kk = k & 255;
    const size_t off = (size_t)row * DDIM + kk;
    const int region = k >> 8;
    if (region == 0) return *reinterpret_cast<const float4*>(X + off);
    float4 m0 = *reinterpret_cast<const float4*>(g_M + off);
    float4 m1 = *reinterpret_cast<const float4*>(g_M + (size_t)NROWS * DDIM + off);
    float4 m2 = *reinterpret_cast<const float4*>(g_M + 2 * (size_t)NROWS * DDIM + off);
    float4 s1;
    s1.x = m0.x + m1.x + m2.x;  s1.y = m0.y + m1.y + m2.y;
    s1.z = m0.z + m1.z + m2.z;  s1.w = m0.w + m1.w + m2.w;
    if (region == 1) return s1;
    float4 s2;
    s2.x = 0.5f * (s1.x * s1.x + m0.x * m0.x + m1.x * m1.x + m2.x * m2.x);
    s2.y = 0.5f * (s1.y * s1.y + m0.y * m0.y + m1.y * m1.y + m2.y * m2.y);
    s2.z = 0.5f * (s1.z * s1.z + m0.z * m0.z + m1.z * m1.z + m2.z * m2.z);
    s2.w = 0.5f * (s1.w * s1.w + m0.w * m0.w + m1.w * m1.w + m2.w * m2.w);
    return s2;
}

// ===== epilogue GEMM (HMMA bf16 3-term): out = relu(T @ W^T + bias), M=32 =====
__global__ __launch_bounds__(256, 2)
void gemm_epi_kernel(const float* __restrict__ X, float* __restrict__ C) {
    extern __shared__ char sm[];

    const int tid  = threadIdx.x;
    const int wid  = tid >> 5;
    const int lane = tid & 31;
    const int g    = lane >> 2;
    const int t4   = lane & 3;
    const int m0w  = (wid >> 2) * 16;
    const int n0w  = (wid & 3) * 64;
    const int bx = blockIdx.x;

    const int arw = tid >> 3, acl = tid & 7;
    const int aRowG = bx * 32 + arw;
    const uint32_t aHiDst = smem_u32(sm) + EAH_OFF + arw * APITCH + acl * 8;
    const uint32_t aLoDst = smem_u32(sm) + EAL_OFF + arw * APITCH + acl * 8;
    const __nv_bfloat16* bSrc[8];
    uint32_t bDst[8];
    #pragma unroll
    for (int j = 0; j < 8; j++) {
        int idx = j * 256 + tid;
        int half_ = idx >> 10;
        int q = idx & 1023;
        int n = q >> 2, c = q & 3;
        bSrc[j] = (half_ ? g_Wbl : g_Wbh) + (size_t)n * KEPI + c * 8;
        bDst[j] = smem_u32(sm) + (half_ ? EBL_OFF : EBH_OFF) + n * BPITCH + c * 16;
    }

    const int aRow = m0w + (lane & 7) + ((lane >> 3) & 1) * 8;
    const int aCol = ((lane >> 4) & 1) * 16;
    const uint32_t aBaseH = smem_u32(sm) + EAH_OFF + aRow * APITCH + aCol;
    const uint32_t aBaseL = smem_u32(sm) + EAL_OFF + aRow * APITCH + aCol;
    const int bRow = n0w + ((lane >> 4) & 1) * 8 + (lane & 7);
    const int bCol = ((lane >> 3) & 1) * 16;
    const uint32_t bBaseH = smem_u32(sm) + EBH_OFF + bRow * BPITCH + bCol;
    const uint32_t bBaseL = smem_u32(sm) + EBL_OFF + bRow * BPITCH + bCol;

    float acc[8][4];
    #pragma unroll
    for (int nf = 0; nf < 8; nf++)
        #pragma unroll
        for (int q = 0; q < 4; q++) acc[nf][q] = 0.0f;

    {
        float4 av = loadT(X, aRowG, acl * 4);
        #pragma unroll
        for (int j = 0; j < 8; j++) cp16(bDst[j], bSrc[j]);
        cp_commit();
        split_sts(aHiDst, aLoDst, av);
        cp_wait0();
        __syncthreads();
    }

    for (int t = 0; t < NCHUNK_E; t++) {
        const int cur = t & 1, nxt = cur ^ 1;
        const bool more = (t + 1 < NCHUNK_E);
        float4 av;
        if (more) {
            av = loadT(X, aRowG, (t + 1) * KC + acl * 4);
            #pragma unroll
            for (int j = 0; j < 8; j++)
                cp16(bDst[j] + nxt * ESTG, bSrc[j] + (size_t)(t + 1) * KC);
            cp_commit();
        }

        const uint32_t soff = cur * ESTG;
        #pragma unroll
        for (int j16 = 0; j16 < 2; j16++) {
            const int kb = j16 * 32;
            uint32_t ah[4], al[4];
            ldsm4(ah, aBaseH + soff + kb);
            ldsm4(al, aBaseL + soff + kb);
            #pragma unroll
            for (int np = 0; np < 4; np++) {
                uint32_t bh[4], bl[4];
                ldsm4(bh, bBaseH + soff + np * 16 * BPITCH + kb);
                ldsm4(bl, bBaseL + soff + np * 16 * BPITCH + kb);
                #pragma unroll
                for (int h = 0; h < 2; h++) {
                    const int nf = 2 * np + h;
                    uint32_t b0h = bh[2 * h], b1h = bh[2 * h + 1];
                    uint32_t b0l = bl[2 * h], b1l = bl[2 * h + 1];
                    mma16816(acc[nf], ah, b0h, b1h);
                    mma16816(acc[nf], al, b0h, b1h);
                    mma16816(acc[nf], ah, b0l, b1l);
                }
            }
        }

        if (more)
            split_sts(aHiDst + nxt * ESTG, aLoDst + nxt * ESTG, av);
        cp_wait0();
        __syncthreads();
    }

    float* Cp = C + (size_t)(bx * 32) * DDIM;
    #pragma unroll
    for (int nf = 0; nf < 8; nf++) {
        int r = m0w + g;
        int c = n0w + nf * 8 + 2 * t4;
        float2 bias = *reinterpret_cast<const float2*>(g_bias + c);
        float2 v0 = make_float2(fmaxf(acc[nf][0] + bias.x, 0.0f),
                                fmaxf(acc[nf][1] + bias.y, 0.0f));
        float2 v1 = make_float2(fmaxf(acc[nf][2] + bias.x, 0.0f),
                                fmaxf(acc[nf][3] + bias.y, 0.0f));
        *reinterpret_cast<float2*>(Cp + (size_t)r * DDIM + c)       = v0;
        *reinterpret_cast<float2*>(Cp + (size_t)(r + 8) * DDIM + c) = v1;
    }
}

// =============== launch ===============
extern "C" void kernel_launch(void* const* d_in, const int* in_sizes, int n_in,
                              void* d_out, int out_size) {
    const float *X = nullptr, *A = nullptr, *W = nullptr, *b = nullptr;
    for (int i = 0; i < n_in; i++) {
        long long s = in_sizes[i];
        if      (s == (long long)PP * NROWS * NROWS) A = (const float*)d_in[i];
        else if (s == (long long)NROWS * DDIM)       X = (const float*)d_in[i];
        else if (s == (long long)PP * DDIM * DDIM)   W = (const float*)d_in[i];
        else if (s == (long long)PP * DDIM)          b = (const float*)d_in[i];
    }
    cudaFuncSetAttribute(gemm1_kernel,
                         cudaFuncAttributeMaxDynamicSharedMemorySize, G1_SMEM);
    cudaFuncSetAttribute(gemm_epi_kernel,
                         cudaFuncAttributeMaxDynamicSharedMemorySize, EPI_SMEM);

    prep_kernel<<<(3 * DDIM * DDIM + 255) / 256, 256>>>(W, b);
    xt_kernel<<<dim3(NROWS / 32, DDIM / 32), dim3(32, 8)>>>(X);
    gemm1_kernel<<<dim3(NROWS / 64, PP), 256, G1_SMEM>>>(A);
    gemm_epi_kernel<<<NROWS / 32, 256, EPI_SMEM>>>(X, (float*)d_out);
}

// round 17
// speedup vs baseline: 2.8048x; 1.2781x over previous
#include <cuda_runtime.h>
#include <cuda_bf16.h>
#include <cuda_fp16.h>
#include <cstdint>

#define NROWS 8192
#define DDIM  256
#define PP    3
#define KEPI   (3 * DDIM)        // 768

// gemm1: BK=64, 144B-pitch rows, A single fp16 + B single fp16
#define KC1    64
#define NCHUNK1 (NROWS / KC1)    // 128
#define G1PITCH 144
#define G1A_OFF 0
#define G1B_OFF 9216
#define G1STG   46080            // 9216 + 256*144
#define G1_SMEM (2 * G1STG)      // 92160

// epi: BK=32, 80B-pitch rows, bf16 3-term (unchanged from R13)
#define KC2    32
#define NCHUNK_E (KEPI / KC2)    // 24
#define EPITCH 80
#define EAH_OFF 0
#define EAL_OFF 2560
#define EBH_OFF 5120
#define EBL_OFF 25600
#define ESTG    46080
#define EPI_SMEM (2 * ESTG)      // 92160

// ---- scratch (device globals; no allocation allowed) ----
__device__ __align__(16) float g_M[PP * NROWS * DDIM];
__device__ __align__(16) float g_bias[DDIM];
__device__ __align__(16) __half g_Xtf[DDIM * NROWS];          // X^T fp16 [d][k]
__device__ __align__(16) __nv_bfloat16 g_Wbh[DDIM * KEPI];    // W as B[n][k] hi
__device__ __align__(16) __nv_bfloat16 g_Wbl[DDIM * KEPI];    // W as B[n][k] lo

// =============== helpers ===============
__device__ __forceinline__ unsigned smem_u32(const void* p) {
    return (unsigned)__cvta_generic_to_shared(p);
}
__device__ __forceinline__ void cp16(unsigned dst, const void* src) {
    asm volatile("cp.async.cg.shared.global [%0], [%1], 16;" :: "r"(dst), "l"(src));
}
__device__ __forceinline__ void cp_commit() { asm volatile("cp.async.commit_group;"); }
__device__ __forceinline__ void cp_wait0()  { asm volatile("cp.async.wait_group 0;"); }

__device__ __forceinline__ void sts64(uint32_t addr, uint32_t v0, uint32_t v1) {
    asm volatile("st.shared.v2.b32 [%0], {%1, %2};" :: "r"(addr), "r"(v0), "r"(v1) : "memory");
}

// ldmatrix x4 (sm_75+, legal at plain sm_103)
__device__ __forceinline__ void ldsm4(uint32_t* r, uint32_t addr) {
    asm volatile("ldmatrix.sync.aligned.m8n8.x4.shared.b16 {%0,%1,%2,%3}, [%4];"
                 : "=r"(r[0]), "=r"(r[1]), "=r"(r[2]), "=r"(r[3]) : "r"(addr));
}

// HMMA m16n8k16 bf16 (epi)
__device__ __forceinline__ void mma16816(float* c, const uint32_t* a,
                                         uint32_t b0, uint32_t b1) {
    asm("mma.sync.aligned.m16n8k16.row.col.f32.bf16.bf16.f32 "
        "{%0,%1,%2,%3}, {%4,%5,%6,%7}, {%8,%9}, {%0,%1,%2,%3};"
        : "+f"(c[0]), "+f"(c[1]), "+f"(c[2]), "+f"(c[3])
        : "r"(a[0]), "r"(a[1]), "r"(a[2]), "r"(a[3]), "r"(b0), "r"(b1));
}
// HMMA m16n8k16 fp16 (gemm1)
__device__ __forceinline__ void mma16816h(float* c, const uint32_t* a,
                                          uint32_t b0, uint32_t b1) {
    asm("mma.sync.aligned.m16n8k16.row.col.f32.f16.f16.f32 "
        "{%0,%1,%2,%3}, {%4,%5,%6,%7}, {%8,%9}, {%0,%1,%2,%3};"
        : "+f"(c[0]), "+f"(c[1]), "+f"(c[2]), "+f"(c[3])
        : "r"(a[0]), "r"(a[1]), "r"(a[2]), "r"(a[3]), "r"(b0), "r"(b1));
}

// bf16 hi/lo split store (epi producer)
__device__ __forceinline__ void split_sts(uint32_t hiAddr, uint32_t loAddr, float4 v) {
    __nv_bfloat162 h01 = __floats2bfloat162_rn(v.x, v.y);
    __nv_bfloat162 h23 = __floats2bfloat162_rn(v.z, v.w);
    float2 f01 = __bfloat1622float2(h01);
    float2 f23 = __bfloat1622float2(h23);
    __nv_bfloat162 l01 = __floats2bfloat162_rn(v.x - f01.x, v.y - f01.y);
    __nv_bfloat162 l23 = __floats2bfloat162_rn(v.z - f23.x, v.w - f23.y);
    sts64(hiAddr, *reinterpret_cast<uint32_t*>(&h01), *reinterpret_cast<uint32_t*>(&h23));
    sts64(loAddr, *reinterpret_cast<uint32_t*>(&l01), *reinterpret_cast<uint32_t*>(&l23));
}
// plain fp16 convert store (gemm1 producer)
__device__ __forceinline__ void cvt_sts_h(uint32_t addr, float4 v) {
    __half2 h01 = __floats2half2_rn(v.x, v.y);
    __half2 h23 = __floats2half2_rn(v.z, v.w);
    sts64(addr, *reinterpret_cast<uint32_t*>(&h01), *reinterpret_cast<uint32_t*>(&h23));
}

// =============== X^T transpose + fp16 convert ===============
__global__ void xt_kernel(const float* __restrict__ X) {
    __shared__ float tile[32][33];
    int k0 = blockIdx.x * 32, d0 = blockIdx.y * 32;
    int tx = threadIdx.x, ty = threadIdx.y;     // 32 x 8
    #pragma unroll
    for (int i = 0; i < 4; i++)
        tile[ty + 8 * i][tx] = X[(size_t)(k0 + ty + 8 * i) * DDIM + d0 + tx];
    __syncthreads();
    #pragma unroll
    for (int i = 0; i < 4; i++) {
        int d = d0 + ty + 8 * i, k = k0 + tx;
        g_Xtf[(size_t)d * NROWS + k] = __float2half_rn(tile[tx][ty + 8 * i]);
    }
}

// =============== prep: W -> B[n][k] bf16 hi/lo + fused bias ===============
__global__ void prep_kernel(const float* __restrict__ W, const float* __restrict__ b) {
    int idx = blockIdx.x * blockDim.x + threadIdx.x;
    if (idx < 3 * DDIM * DDIM) {
        int kk = idx & (DDIM - 1);
        int rd = idx >> 8;
        int d  = rd & (DDIM - 1);
        int r  = rd >> 8;
        float v = W[idx];
        __nv_bfloat16 h = __float2bfloat16(v);
        __nv_bfloat16 l = __float2bfloat16(v - __bfloat162float(h));
        int k = r * DDIM + kk;
        g_Wbh[d * KEPI + k] = h;
        g_Wbl[d * KEPI + k] = l;
    }
    if (idx < DDIM)
        g_bias[idx] = b[idx] + 3.0f * b[DDIM + idx] + 6.0f * b[2 * DDIM + idx];
}

// ===== gemm1: M_p = A_p @ X  (HMMA fp16 single-term, BK=64) ====================
// CTA: 64 x 256, 256 threads, 8 warps (2 m-groups x 4 n-groups),
// warp tile 32 x 64. 64 MMAs per warp per chunk; 128 chunks.
__global__ __launch_bounds__(256, 2)
void gemm1_kernel(const float* __restrict__ A) {
    extern __shared__ char sm[];

    const int tid  = threadIdx.x;
    const int wid  = tid >> 5;
    const int lane = tid & 31;
    const int g    = lane >> 2;
    const int t4   = lane & 3;
    const int m0w  = (wid >> 2) * 32;
    const int n0w  = (wid & 3) * 64;
    const int bx = blockIdx.x, p = blockIdx.y;

    const float* Ap = A + (size_t)p * NROWS * NROWS + (size_t)bx * 64 * NROWS;

    // producer A: 64 rows x 16 float4 = 1024 -> 4 per thread
    const float* aSrc[4];
    uint32_t aDst[4];
    #pragma unroll
    for (int j = 0; j < 4; j++) {
        int idx = j * 256 + tid;
        int r = idx >> 4, c = idx & 15;     // row 0..63, float4-col 0..15
        aSrc[j] = Ap + (size_t)r * NROWS + c * 4;
        aDst[j] = smem_u32(sm) + G1A_OFF + r * G1PITCH + c * 8;
    }
    // producer B: 256 rows x 128B = 2048 cp16 -> 8 per thread
    const __half* bSrc[8];
    uint32_t bDst[8];
    #pragma unroll
    for (int j = 0; j < 8; j++) {
        int idx = j * 256 + tid;            // 0..2047
        int n = idx >> 3, c = idx & 7;      // row 0..255, 16B chunk 0..7
        bSrc[j] = g_Xtf + (size_t)n * NROWS + c * 8;
        bDst[j] = smem_u32(sm) + G1B_OFF + n * G1PITCH + c * 16;
    }

    const int aRow = m0w + (lane & 7) + ((lane >> 3) & 1) * 8;
    const int aCol = ((lane >> 4) & 1) * 16;
    const uint32_t aBase = smem_u32(sm) + G1A_OFF + aRow * G1PITCH + aCol;
    const int bRow = n0w + ((lane >> 4) & 1) * 8 + (lane & 7);
    const int bCol = ((lane >> 3) & 1) * 16;
    const uint32_t bBase = smem_u32(sm) + G1B_OFF + bRow * G1PITCH + bCol;

    float acc[2][8][4];
    #pragma unroll
    for (int mf = 0; mf < 2; mf++)
        #pragma unroll
        for (int nf = 0; nf < 8; nf++)
            #pragma unroll
            for (int q = 0; q < 4; q++) acc[mf][nf][q] = 0.0f;

    {
        float4 av[4];
        #pragma unroll
        for (int j = 0; j < 4; j++) av[j] = *reinterpret_cast<const float4*>(aSrc[j]);
        #pragma unroll
        for (int j = 0; j < 8; j++) cp16(bDst[j], bSrc[j]);
        cp_commit();
        #pragma unroll
        for (int j = 0; j < 4; j++) cvt_sts_h(aDst[j], av[j]);
        cp_wait0();
        __syncthreads();
    }

    for (int t = 0; t < NCHUNK1; t++) {
        const int cur = t & 1, nxt = cur ^ 1;
        const bool more = (t + 1 < NCHUNK1);
        float4 av[4];
        if (more) {
            #pragma unroll
            for (int j = 0; j < 4; j++)
                av[j] = *reinterpret_cast<const float4*>(aSrc[j] + (size_t)(t + 1) * KC1);
            #pragma unroll
            for (int j = 0; j < 8; j++)
                cp16(bDst[j] + nxt * G1STG, bSrc[j] + (size_t)(t + 1) * KC1);
            cp_commit();
        }

        const uint32_t soff = cur * G1STG;
        #pragma unroll
        for (int j16 = 0; j16 < 4; j16++) {
            const int kb = j16 * 32;
            uint32_t ah[2][4];
            ldsm4(ah[0], aBase + soff + kb);
            ldsm4(ah[1], aBase + soff + 16 * G1PITCH + kb);
            #pragma unroll
            for (int np = 0; np < 4; np++) {
                uint32_t bq[4];
                ldsm4(bq, bBase + soff + np * 16 * G1PITCH + kb);
                #pragma unroll
                for (int h = 0; h < 2; h++) {
                    const int nf = 2 * np + h;
                    uint32_t b0 = bq[2 * h], b1 = bq[2 * h + 1];
                    #pragma unroll
                    for (int mf = 0; mf < 2; mf++)
                        mma16816h(acc[mf][nf], ah[mf], b0, b1);
                }
            }
        }

        if (more) {
            #pragma unroll
            for (int j = 0; j < 4; j++)
                cvt_sts_h(aDst[j] + nxt * G1STG, av[j]);
        }
        cp_wait0();
        __syncthreads();
    }

    float* Mout = g_M + (size_t)p * NROWS * DDIM + (size_t)bx * 64 * DDIM;
    #pragma unroll
    for (int mf = 0; mf < 2; mf++) {
        #pragma unroll
        for (int nf = 0; nf < 8; nf++) {
            int r = m0w + mf * 16 + g;
            int c = n0w + nf * 8 + 2 * t4;
            *reinterpret_cast<float2*>(Mout + (size_t)r * DDIM + c) =
                make_float2(acc[mf][nf][0], acc[mf][nf][1]);
            *reinterpret_cast<float2*>(Mout + (size_t)(r + 8) * DDIM + c) =
                make_float2(acc[mf][nf][2], acc[mf][nf][3]);
        }
    }
}

// ===== T row compute on the fly: region = k>>8, uniform per chunk =====
__device__ __forceinline__ float4 loadT(const float* __restrict__ X, int row, int k) {
    const int kk = k & 255;
    const size_t off = (size_t)row * DDIM + kk;
    const int region = k >> 8;
    if (region == 0) return *reinterpret_cast<const float4*>(X + off);
    float4 m0 = *reinterpret_cast<const float4*>(g_M + off);
    float4 m1 = *reinterpret_cast<const float4*>(g_M + (size_t)NROWS * DDIM + off);
    float4 m2 = *reinterpret_cast<const float4*>(g_M + 2 * (size_t)NROWS * DDIM + off);
    float4 s1;
    s1.x = m0.x + m1.x + m2.x;  s1.y = m0.y + m1.y + m2.y;
    s1.z = m0.z + m1.z + m2.z;  s1.w = m0.w + m1.w + m2.w;
    if (region == 1) return s1;
    float4 s2;
    s2.x = 0.5f * (s1.x * s1.x + m0.x * m0.x + m1.x * m1.x + m2.x * m2.x);
    s2.y = 0.5f * (s1.y * s1.y + m0.y * m0.y + m1.y * m1.y + m2.y * m2.y);
    s2.z = 0.5f * (s1.z * s1.z + m0.z * m0.z + m1.z * m1.z + m2.z * m2.z);
    s2.w = 0.5f * (s1.w * s1.w + m0.w * m0.w + m1.w * m1.w + m2.w * m2.w);
    return s2;
}

// ===== epilogue GEMM (HMMA bf16 3-term): out = relu(T @ W^T + bias), M=32 =====
__global__ __launch_bounds__(256, 2)
void gemm_epi_kernel(const float* __restrict__ X, float* __restrict__ C) {
    extern __shared__ char sm[];

    const int tid  = threadIdx.x;
    const int wid  = tid >> 5;
    const int lane = tid & 31;
    const int g    = lane >> 2;
    const int t4   = lane & 3;
    const int m0w  = (wid >> 2) * 16;
    const int n0w  = (wid & 3) * 64;
    const int bx = blockIdx.x;

    const int arw = tid >> 3, acl = tid & 7;
    const int aRowG = bx * 32 + arw;
    const uint32_t aHiDst = smem_u32(sm) + EAH_OFF + arw * EPITCH + acl * 8;
    const uint32_t aLoDst = smem_u32(sm) + EAL_OFF + arw * EPITCH + acl * 8;
    const __nv_bfloat16* bSrc[8];
    uint32_t bDst[8];
    #pragma unroll
    for (int j = 0; j < 8; j++) {
        int idx = j * 256 + tid;
        int half_ = idx >> 10;
        int q = idx & 1023;
        int n = q >> 2, c = q & 3;
        bSrc[j] = (half_ ? g_Wbl : g_Wbh) + (size_t)n * KEPI + c * 8;
        bDst[j] = smem_u32(sm) + (half_ ? EBL_OFF : EBH_OFF) + n * EPITCH + c * 16;
    }

    const int aRow = m0w + (lane & 7) + ((lane >> 3) & 1) * 8;
    const int aCol = ((lane >> 4) & 1) * 16;
    const uint32_t aBaseH = smem_u32(sm) + EAH_OFF + aRow * EPITCH + aCol;
    const uint32_t aBaseL = smem_u32(sm) + EAL_OFF + aRow * EPITCH + aCol;
    const int bRow = n0w + ((lane >> 4) & 1) * 8 + (lane & 7);
    const int bCol = ((lane >> 3) & 1) * 16;
    const uint32_t bBaseH = smem_u32(sm) + EBH_OFF + bRow * EPITCH + bCol;
    const uint32_t bBaseL = smem_u32(sm) + EBL_OFF + bRow * EPITCH + bCol;

    float acc[8][4];
    #pragma unroll
    for (int nf = 0; nf < 8; nf++)
        #pragma unroll
        for (int q = 0; q < 4; q++) acc[nf][q] = 0.0f;

    {
        float4 av = loadT(X, aRowG, acl * 4);
        #pragma unroll
        for (int j = 0; j < 8; j++) cp16(bDst[j], bSrc[j]);
        cp_commit();
        split_sts(aHiDst, aLoDst, av);
        cp_wait0();
        __syncthreads();
    }

    for (int t = 0; t < NCHUNK_E; t++) {
        const int cur = t & 1, nxt = cur ^ 1;
        const bool more = (t + 1 < NCHUNK_E);
        float4 av;
        if (more) {
            av = loadT(X, aRowG, (t + 1) * KC2 + acl * 4);
            #pragma unroll
            for (int j = 0; j < 8; j++)
                cp16(bDst[j] + nxt * ESTG, bSrc[j] + (size_t)(t + 1) * KC2);
            cp_commit();
        }

        const uint32_t soff = cur * ESTG;
        #pragma unroll
        for (int j16 = 0; j16 < 2; j16++) {
            const int kb = j16 * 32;
            uint32_t ah[4], al[4];
            ldsm4(ah, aBaseH + soff + kb);
            ldsm4(al, aBaseL + soff + kb);
            #pragma unroll
            for (int np = 0; np < 4; np++) {
                uint32_t bh[4], bl[4];
                ldsm4(bh, bBaseH + soff + np * 16 * EPITCH + kb);
                ldsm4(bl, bBaseL + soff + np * 16 * EPITCH + kb);
                #pragma unroll
                for (int h = 0; h < 2; h++) {
                    const int nf = 2 * np + h;
                    uint32_t b0h = bh[2 * h], b1h = bh[2 * h + 1];
                    uint32_t b0l = bl[2 * h], b1l = bl[2 * h + 1];
                    mma16816(acc[nf], ah, b0h, b1h);
                    mma16816(acc[nf], al, b0h, b1h);
                    mma16816(acc[nf], ah, b0l, b1l);
                }
            }
        }

        if (more)
            split_sts(aHiDst + nxt * ESTG, aLoDst + nxt * ESTG, av);
        cp_wait0();
        __syncthreads();
    }

    float* Cp = C + (size_t)(bx * 32) * DDIM;
    #pragma unroll
    for (int nf = 0; nf < 8; nf++) {
        int r = m0w + g;
        int c = n0w + nf * 8 + 2 * t4;
        float2 bias = *reinterpret_cast<const float2*>(g_bias + c);
        float2 v0 = make_float2(fmaxf(acc[nf][0] + bias.x, 0.0f),
                                fmaxf(acc[nf][1] + bias.y, 0.0f));
        float2 v1 = make_float2(fmaxf(acc[nf][2] + bias.x, 0.0f),
                                fmaxf(acc[nf][3] + bias.y, 0.0f));
        *reinterpret_cast<float2*>(Cp + (size_t)r * DDIM + c)       = v0;
        *reinterpret_cast<float2*>(Cp + (size_t)(r + 8) * DDIM + c) = v1;
    }
}

// =============== launch ===============
extern "C" void kernel_launch(void* const* d_in, const int* in_sizes, int n_in,
                              void* d_out, int out_size) {
    const float *X = nullptr, *A = nullptr, *W = nullptr, *b = nullptr;
    for (int i = 0; i < n_in; i++) {
        long long s = in_sizes[i];
        if      (s == (long long)PP * NROWS * NROWS) A = (const float*)d_in[i];
        else if (s == (long long)NROWS * DDIM)       X = (const float*)d_in[i];
        else if (s == (long long)PP * DDIM * DDIM)   W = (const float*)d_in[i];
        else if (s == (long long)PP * DDIM)          b = (const float*)d_in[i];
    }
    cudaFuncSetAttribute(gemm1_kernel,
                         cudaFuncAttributeMaxDynamicSharedMemorySize, G1_SMEM);
    cudaFuncSetAttribute(gemm_epi_kernel,
                         cudaFuncAttributeMaxDynamicSharedMemorySize, EPI_SMEM);

    prep_kernel<<<(3 * DDIM * DDIM + 255) / 256, 256>>>(W, b);
    xt_kernel<<<dim3(NROWS / 32, DDIM / 32), dim3(32, 8)>>>(X);
    gemm1_kernel<<<dim3(NROWS / 64, PP), 256, G1_SMEM>>>(A);
    gemm_epi_kernel<<<NROWS / 32, 256, EPI_SMEM>>>(X, (float*)d_out);
}